// round 1
// baseline (speedup 1.0000x reference)
#include <cuda_runtime.h>
#include <cuda_bf16.h>
#include <math.h>

// ---------------------------------------------------------------------------
// Problem constants
// ---------------------------------------------------------------------------
#define BATCH   16
#define NH      8
#define HID     128
#define VD      16
#define RIN     64          // input res (64x64)
#define RLAT    32          // latent res (32x32)
#define NIN     (RIN*RIN)   // 4096
#define NLAT    (RLAT*RLAT) // 1024
#define PI_F    3.14159265358979323846f

// ---------------------------------------------------------------------------
// Scratch buffers (static device globals -- no allocation anywhere)
// ---------------------------------------------------------------------------
__device__ float g_h0 [BATCH*NIN*HID];   // encoder out / reused as decoder tmp
__device__ float g_val[BATCH*NIN*HID];   // value projection (max size)
__device__ float g_hup[BATCH*NIN*HID];   // up-attention output
__device__ float g_hA [BATCH*NLAT*HID];
__device__ float g_hB [BATCH*NLAT*HID];
__device__ float g_pa [BATCH*NLAT*HID];
__device__ float g_t1 [BATCH*NLAT*HID];
__device__ float g_t2 [BATCH*NLAT*HID];
__device__ float g_wall[HID*HID];        // rearranged per-head value weights
__device__ int   g_kidx[NLAT*64];
__device__ int   g_kcnt[NLAT];

// ---------------------------------------------------------------------------
// Helpers
// ---------------------------------------------------------------------------
__device__ __forceinline__ float gelu_f(float x) {
    const float c = 0.7978845608028654f;  // sqrt(2/pi)
    float x3 = x * x * x;
    return 0.5f * x * (1.0f + tanhf(c * (x + 0.044715f * x3)));
}

__device__ __forceinline__ float head_scale(float r) {
    return tanf(0.25f * PI_F * (1.0f - 1e-7f) * (1.0f + sinf(r)));
}

// ---------------------------------------------------------------------------
// kNN precompute for proc locality mask (2nd percentile => keep dv <= dv20)
// dv20 = 21st smallest (0-indexed rank 20) squared integer grid offset.
// ---------------------------------------------------------------------------
__global__ void k_knn(int* __restrict__ kidx, int* __restrict__ kcnt) {
    int q = blockIdx.x;
    int tid = threadIdx.x;                  // 256 threads, 4 keys each
    int qx = q & (RLAT - 1), qy = q >> 5;
    int dv[4];
#pragma unroll
    for (int i = 0; i < 4; i++) {
        int k = tid * 4 + i;
        int kx = k & (RLAT - 1), ky = k >> 5;
        int dx = qx - kx, dy = qy - ky;
        dv[i] = dx * dx + dy * dy;
    }
    __shared__ int scount;
    int lo = 0, hi = 2 * 31 * 31;
    while (lo < hi) {
        int mid = (lo + hi) >> 1;
        if (tid == 0) scount = 0;
        __syncthreads();
        int c = 0;
#pragma unroll
        for (int i = 0; i < 4; i++) c += (dv[i] <= mid);
#pragma unroll
        for (int o = 16; o > 0; o >>= 1) c += __shfl_down_sync(0xffffffffu, c, o);
        if ((tid & 31) == 0) atomicAdd(&scount, c);
        __syncthreads();
        if (scount >= 21) hi = mid; else lo = mid + 1;
        __syncthreads();
    }
    // deterministic serial collection (ascending key order)
    if (tid == 0) {
        int n = 0;
        for (int k = 0; k < NLAT && n < 64; k++) {
            int kx = k & (RLAT - 1), ky = k >> 5;
            int dx = qx - kx, dy = qy - ky;
            if (dx * dx + dy * dy <= lo) kidx[q * 64 + (n++)] = k;
        }
        kcnt[q] = n;
    }
}

// ---------------------------------------------------------------------------
// Encoder: out[b,n,c] = gelu(sum_j x[b,n,j]*W[j,c] + bias[c]),  K=3
// ---------------------------------------------------------------------------
__global__ void k_enc(const float* __restrict__ x, const float* __restrict__ w,
                      const float* __restrict__ bias, float* __restrict__ out) {
    int idx = blockIdx.x * 256 + threadIdx.x;   // BATCH*NIN*HID threads
    int c = idx & (HID - 1);
    int bn = idx >> 7;
    float a = fmaf(x[bn * 3 + 0], w[c],
              fmaf(x[bn * 3 + 1], w[HID + c],
              fmaf(x[bn * 3 + 2], w[2 * HID + c], bias[c])));
    out[idx] = gelu_f(a);
}

// ---------------------------------------------------------------------------
// Rearrange per-head value weights [H][128][16] -> Wall[128][128] (c = h*16+vd)
// ---------------------------------------------------------------------------
__global__ void k_wrearr(const float* __restrict__ w, float* __restrict__ wall) {
    int idx = blockIdx.x * 256 + threadIdx.x;   // 16384
    int j = idx >> 7, c = idx & (HID - 1);
    int h = c >> 4, vd = c & 15;
    wall[idx] = w[(h * HID + j) * VD + vd];
}

// ---------------------------------------------------------------------------
// Generic 128-K GEMM: C[row][:] = act(A[row][:] @ W + bias (+ addsrc[row][:]))
// BM=64, BN=128, BK=32, 256 threads, 8x4 micro-tile.
// ---------------------------------------------------------------------------
__global__ void k_gemm128(const float* __restrict__ A, const float* __restrict__ W,
                          const float* __restrict__ bias, const float* __restrict__ addsrc,
                          float* __restrict__ C, int dogelu) {
    __shared__ float sA[32][65];
    __shared__ float sB[32][128];
    int tid = threadIdx.x;
    int row0 = (tid >> 5) << 3;
    int col0 = (tid & 31) << 2;
    size_t rbase = (size_t)blockIdx.x * 64;
    float acc[8][4];
#pragma unroll
    for (int i = 0; i < 8; i++)
#pragma unroll
        for (int j = 0; j < 4; j++) acc[i][j] = 0.f;

    for (int k0 = 0; k0 < 128; k0 += 32) {
#pragma unroll
        for (int i = 0; i < 8; i++) {
            int idx = tid + i * 256;
            sA[idx & 31][idx >> 5] = A[(rbase + (idx >> 5)) * 128 + k0 + (idx & 31)];
        }
#pragma unroll
        for (int i = 0; i < 16; i++) {
            int idx = tid + i * 256;
            sB[idx >> 7][idx & 127] = W[(k0 + (idx >> 7)) * 128 + (idx & 127)];
        }
        __syncthreads();
#pragma unroll 8
        for (int kk = 0; kk < 32; kk++) {
            float4 bv = *reinterpret_cast<const float4*>(&sB[kk][col0]);
#pragma unroll
            for (int i = 0; i < 8; i++) {
                float a = sA[kk][row0 + i];
                acc[i][0] = fmaf(a, bv.x, acc[i][0]);
                acc[i][1] = fmaf(a, bv.y, acc[i][1]);
                acc[i][2] = fmaf(a, bv.z, acc[i][2]);
                acc[i][3] = fmaf(a, bv.w, acc[i][3]);
            }
        }
        __syncthreads();
    }
    float4 bsv = make_float4(0.f, 0.f, 0.f, 0.f);
    if (bias) bsv = *reinterpret_cast<const float4*>(&bias[col0]);
#pragma unroll
    for (int i = 0; i < 8; i++) {
        size_t row = rbase + row0 + i;
        float4 r;
        r.x = acc[i][0] + bsv.x;
        r.y = acc[i][1] + bsv.y;
        r.z = acc[i][2] + bsv.z;
        r.w = acc[i][3] + bsv.w;
        if (addsrc) {
            float4 s = *reinterpret_cast<const float4*>(&addsrc[row * 128 + col0]);
            r.x += s.x; r.y += s.y; r.z += s.z; r.w += s.w;
        }
        if (dogelu) {
            r.x = gelu_f(r.x); r.y = gelu_f(r.y); r.z = gelu_f(r.z); r.w = gelu_f(r.w);
        }
        *reinterpret_cast<float4*>(&C[row * 128 + col0]) = r;
    }
}

// ---------------------------------------------------------------------------
// Fused dense pos-attention (down / up): per block = (head, 16-query tile).
// Computes softmax row weights on the fly from grid coords, accumulates
// out[b,q,h*16+vd] = gelu( (sum_k p~ * V[b,k,h*16+vd]) / sum_k p~ ).
// V layout: [b][k][128] (natural GEMM output).
// ---------------------------------------------------------------------------
template <int RQ, int RK>
__global__ void k_att(const float* __restrict__ V, const float* __restrict__ rv,
                      float* __restrict__ out) {
    constexpr int Nq = RQ * RQ, Nk = RK * RK;
    constexpr int QT = 16, KT = 32;
    __shared__ float sv[KT][256];
    __shared__ float sp[QT][KT];
    __shared__ float ssum[QT];
    __shared__ float smind[QT];
    __shared__ float sscale;

    int tid = threadIdx.x;       // 256
    int h = blockIdx.y;
    int q0 = blockIdx.x * QT;

    if (tid == 0) sscale = head_scale(rv[h]);
    if (tid < QT) {
        int q = q0 + tid;
        float qx = (float)(q % RQ) * (1.0f / RQ);
        float qy = (float)(q / RQ) * (1.0f / RQ);
        float mx = 1e30f, my = 1e30f;
        for (int k = 0; k < RK; k++) {
            float dx = qx - k * (1.0f / RK); dx *= dx; mx = fminf(mx, dx);
            float dy = qy - k * (1.0f / RK); dy *= dy; my = fminf(my, dy);
        }
        smind[tid] = 0.5f * (mx + my);
        ssum[tid] = 0.f;
    }
    __syncthreads();
    float scale = sscale;

    float acc[QT];
#pragma unroll
    for (int i = 0; i < QT; i++) acc[i] = 0.f;

    int b = tid >> 4, vd = tid & 15;
    const float* Vb = V + ((size_t)b * Nk) * 128 + h * 16 + vd;

    // sp-computation assignment: 2 entries per thread
    int sqq = tid >> 4;              // 0..15
    int skk = (tid & 15) * 2;        // 0,2,..,30
    float sqx, sqy;
    {
        int q = q0 + sqq;
        sqx = (float)(q % RQ) * (1.0f / RQ);
        sqy = (float)(q / RQ) * (1.0f / RQ);
    }
    float mind = smind[sqq];

    for (int k0 = 0; k0 < Nk; k0 += KT) {
#pragma unroll
        for (int kk = 0; kk < KT; kk++) sv[kk][tid] = Vb[(size_t)(k0 + kk) * 128];
        {
            float psum = 0.f;
#pragma unroll
            for (int j = 0; j < 2; j++) {
                int k = k0 + skk + j;
                float kx = (float)(k % RK) * (1.0f / RK);
                float ky = (float)(k / RK) * (1.0f / RK);
                float dx = sqx - kx, dy = sqy - ky;
                float dist = 0.5f * (dx * dx + dy * dy);
                float p = __expf(scale * (mind - dist));  // <= 1, stable
                sp[sqq][skk + j] = p;
                psum += p;
            }
            psum += __shfl_down_sync(0xffffffffu, psum, 8, 16);
            psum += __shfl_down_sync(0xffffffffu, psum, 4, 16);
            psum += __shfl_down_sync(0xffffffffu, psum, 2, 16);
            psum += __shfl_down_sync(0xffffffffu, psum, 1, 16);
            if ((tid & 15) == 0) ssum[sqq] += psum;
        }
        __syncthreads();
#pragma unroll 2
        for (int kk = 0; kk < KT; kk += 4) {
            float v0 = sv[kk][tid], v1 = sv[kk + 1][tid];
            float v2 = sv[kk + 2][tid], v3 = sv[kk + 3][tid];
#pragma unroll
            for (int qq = 0; qq < QT; qq++) {
                float4 p = *reinterpret_cast<const float4*>(&sp[qq][kk]);
                acc[qq] = fmaf(p.x, v0, acc[qq]);
                acc[qq] = fmaf(p.y, v1, acc[qq]);
                acc[qq] = fmaf(p.z, v2, acc[qq]);
                acc[qq] = fmaf(p.w, v3, acc[qq]);
            }
        }
        __syncthreads();
    }
    int outc = h * 16 + vd;
#pragma unroll
    for (int qq = 0; qq < QT; qq++) {
        float v = acc[qq] / ssum[qq];
        out[((size_t)b * Nq + q0 + qq) * 128 + outc] = gelu_f(v);
    }
}

// ---------------------------------------------------------------------------
// Sparse proc attention: per block = one latent query, loop over 8 heads,
// only ~21-32 neighbor keys (precomputed by k_knn). mind = 0 (self in set).
// ---------------------------------------------------------------------------
__global__ void k_procatt(const float* __restrict__ V, const float* __restrict__ rv,
                          const int* __restrict__ kidx, const int* __restrict__ kcnt,
                          float* __restrict__ out) {
    int q = blockIdx.x;           // 1024
    int tid = threadIdx.x;        // 256
    __shared__ int   sidx[64];
    __shared__ float sdist[64];
    __shared__ float sp[64];
    __shared__ float ssum;
    __shared__ float sscale[NH];
    int cnt = kcnt[q];
    if (tid < cnt) {
        int k = kidx[q * 64 + tid];
        sidx[tid] = k;
        int qx = q & 31, qy = q >> 5;
        int kx = k & 31, ky = k >> 5;
        float dx = (qx - kx) * (1.0f / RLAT), dy = (qy - ky) * (1.0f / RLAT);
        sdist[tid] = 0.5f * (dx * dx + dy * dy);
    }
    if (tid < NH) sscale[tid] = head_scale(rv[tid]);
    __syncthreads();
    int b = tid >> 4, vd = tid & 15;
    for (int h = 0; h < NH; h++) {
        if (tid < cnt) sp[tid] = __expf(-sscale[h] * sdist[tid]);
        __syncthreads();
        if (tid == 0) {
            float s = 0.f;
            for (int j = 0; j < cnt; j++) s += sp[j];
            ssum = s;
        }
        __syncthreads();
        float acc = 0.f;
        for (int j = 0; j < cnt; j++)
            acc += sp[j] * V[((size_t)b * NLAT + sidx[j]) * 128 + h * 16 + vd];
        out[((size_t)b * NLAT + q) * 128 + h * 16 + vd] = gelu_f(acc / ssum);
        __syncthreads();
    }
}

// ---------------------------------------------------------------------------
// Final projection 128 -> 1: warp per row
// ---------------------------------------------------------------------------
__global__ void k_dec2(const float* __restrict__ H, const float* __restrict__ w,
                       const float* __restrict__ b0, float* __restrict__ out) {
    int row = blockIdx.x * 8 + (threadIdx.x >> 5);
    int lane = threadIdx.x & 31;
    const float4 h4 = reinterpret_cast<const float4*>(H + (size_t)row * 128)[lane];
    const float4 w4 = reinterpret_cast<const float4*>(w)[lane];
    float s = h4.x * w4.x + h4.y * w4.y + h4.z * w4.z + h4.w * w4.w;
#pragma unroll
    for (int o = 16; o > 0; o >>= 1) s += __shfl_down_sync(0xffffffffu, s, o);
    if (lane == 0) out[row] = s + b0[0];
}

// ---------------------------------------------------------------------------
// Launcher
// ---------------------------------------------------------------------------
extern "C" void kernel_launch(void* const* d_in, const int* in_sizes, int n_in,
                              void* d_out, int out_size) {
    const float* x        = (const float*)d_in[0];
    const float* en_w     = (const float*)d_in[1];
    const float* en_b     = (const float*)d_in[2];
    const float* down_r   = (const float*)d_in[3];
    const float* down_w   = (const float*)d_in[4];
    const float* pa_r     = (const float*)d_in[5];
    const float* pa_w     = (const float*)d_in[6];
    const float* mlp1_w   = (const float*)d_in[7];
    const float* mlp1_b   = (const float*)d_in[8];
    const float* mlp2_w   = (const float*)d_in[9];
    const float* mlp2_b   = (const float*)d_in[10];
    const float* res_w    = (const float*)d_in[11];
    const float* res_b    = (const float*)d_in[12];
    const float* up_r     = (const float*)d_in[13];
    const float* up_w     = (const float*)d_in[14];
    const float* de1_w    = (const float*)d_in[15];
    const float* de1_b    = (const float*)d_in[16];
    const float* de2_w    = (const float*)d_in[17];
    const float* de2_b    = (const float*)d_in[18];
    float* out = (float*)d_out;

    float *h0, *val, *hup, *hA, *hB, *pa, *t1, *t2, *wall;
    int *kidx, *kcnt;
    cudaGetSymbolAddress((void**)&h0,   g_h0);
    cudaGetSymbolAddress((void**)&val,  g_val);
    cudaGetSymbolAddress((void**)&hup,  g_hup);
    cudaGetSymbolAddress((void**)&hA,   g_hA);
    cudaGetSymbolAddress((void**)&hB,   g_hB);
    cudaGetSymbolAddress((void**)&pa,   g_pa);
    cudaGetSymbolAddress((void**)&t1,   g_t1);
    cudaGetSymbolAddress((void**)&t2,   g_t2);
    cudaGetSymbolAddress((void**)&wall, g_wall);
    cudaGetSymbolAddress((void**)&kidx, g_kidx);
    cudaGetSymbolAddress((void**)&kcnt, g_kcnt);

    const int M_IN  = BATCH * NIN;   // 65536
    const int M_LAT = BATCH * NLAT;  // 16384

    // neighbor lists for proc locality mask
    k_knn<<<NLAT, 256>>>(kidx, kcnt);

    // encoder
    k_enc<<<(BATCH * NIN * HID) / 256, 256>>>(x, en_w, en_b, h0);

    // ---- down pos-attention (4096 keys -> 1024 queries) ----
    k_wrearr<<<64, 256>>>(down_w, wall);
    k_gemm128<<<M_IN / 64, 256>>>(h0, wall, nullptr, nullptr, val, 0);
    {
        dim3 g(NLAT / 16, NH);
        k_att<RLAT, RIN><<<g, 256>>>(val, down_r, hA);
    }

    // ---- processor blocks ----
    float* hin = hA;
    float* hout = hB;
    for (int i = 0; i < 3; i++) {
        k_wrearr<<<64, 256>>>(pa_w + (size_t)i * NH * HID * VD, wall);
        k_gemm128<<<M_LAT / 64, 256>>>(hin, wall, nullptr, nullptr, val, 0);
        k_procatt<<<NLAT, 256>>>(val, pa_r + i * NH, kidx, kcnt, pa);
        k_gemm128<<<M_LAT / 64, 256>>>(pa, mlp1_w + (size_t)i * HID * HID,
                                       mlp1_b + i * HID, nullptr, t1, 1);
        k_gemm128<<<M_LAT / 64, 256>>>(t1, mlp2_w + (size_t)i * HID * HID,
                                       mlp2_b + i * HID, nullptr, t2, 0);
        k_gemm128<<<M_LAT / 64, 256>>>(hin, res_w + (size_t)i * HID * HID,
                                       res_b + i * HID, t2, hout, 1);
        float* tmp = hin; hin = hout; hout = tmp;
    }

    // ---- up pos-attention (1024 keys -> 4096 queries) ----
    k_wrearr<<<64, 256>>>(up_w, wall);
    k_gemm128<<<M_LAT / 64, 256>>>(hin, wall, nullptr, nullptr, val, 0);
    {
        dim3 g(NIN / 16, NH);
        k_att<RIN, RLAT><<<g, 256>>>(val, up_r, hup);
    }

    // ---- decoder ----
    k_gemm128<<<M_IN / 64, 256>>>(hup, de1_w, de1_b, nullptr, h0, 1);
    k_dec2<<<M_IN / 8, 256>>>(h0, de2_w, de2_b, out);
}

// round 2
// speedup vs baseline: 3.3456x; 3.3456x over previous
#include <cuda_runtime.h>
#include <cuda_bf16.h>
#include <math.h>

// ---------------------------------------------------------------------------
// Problem constants
// ---------------------------------------------------------------------------
#define BATCH   16
#define NH      8
#define HID     128
#define VD      16
#define RIN     64          // input res (64x64)
#define RLAT    32          // latent res (32x32)
#define NIN     (RIN*RIN)   // 4096
#define NLAT    (RLAT*RLAT) // 1024
#define PI_F    3.14159265358979323846f

typedef unsigned long long ull;

// ---------------------------------------------------------------------------
// Scratch buffers (static device globals -- no allocation anywhere)
// ---------------------------------------------------------------------------
__device__ float g_h0 [BATCH*NIN*HID];   // encoder out / T buffer / decoder tmp
__device__ float g_val[BATCH*NIN*HID];   // value projection (max size)
__device__ float g_hup[BATCH*NIN*HID];   // up-attention output
__device__ float g_hA [BATCH*NLAT*HID];
__device__ float g_hB [BATCH*NLAT*HID];
__device__ float g_pa [BATCH*NLAT*HID];
__device__ float g_t1 [BATCH*NLAT*HID];
__device__ float g_t2 [BATCH*NLAT*HID];
__device__ float g_wall[HID*HID];        // rearranged per-head value weights
__device__ float g_wdn[NH*RLAT*RIN];     // separable factors: down (32q x 64k)
__device__ float g_wup[NH*RIN*RLAT];     // separable factors: up   (64q x 32k)
__device__ int   g_kidx[NLAT*64];
__device__ int   g_kcnt[NLAT];

// ---------------------------------------------------------------------------
// Helpers
// ---------------------------------------------------------------------------
__device__ __forceinline__ float gelu_f(float x) {
    const float c = 0.7978845608028654f;  // sqrt(2/pi)
    float x3 = x * x * x;
    return 0.5f * x * (1.0f + tanhf(c * (x + 0.044715f * x3)));
}

__device__ __forceinline__ float head_scale(float r) {
    return tanf(0.25f * PI_F * (1.0f - 1e-7f) * (1.0f + sinf(r)));
}

__device__ __forceinline__ ull pack2(float x, float y) {
    ull r;
    asm("mov.b64 %0, {%1, %2};" : "=l"(r) : "f"(x), "f"(y));
    return r;
}
__device__ __forceinline__ void ffma2(ull& d, ull a, ull b) {
    asm("fma.rn.f32x2 %0, %1, %2, %3;" : "=l"(d) : "l"(a), "l"(b), "l"(d));
}
__device__ __forceinline__ float lo32(ull v) {
    return __int_as_float((int)(unsigned)(v & 0xffffffffull));
}
__device__ __forceinline__ float hi32(ull v) {
    return __int_as_float((int)(unsigned)(v >> 32));
}

// ---------------------------------------------------------------------------
// kNN precompute for proc locality mask (2nd percentile => keep dv <= dv20)
// ---------------------------------------------------------------------------
__global__ void k_knn(int* __restrict__ kidx, int* __restrict__ kcnt) {
    int q = blockIdx.x;
    int tid = threadIdx.x;                  // 256 threads, 4 keys each
    int qx = q & (RLAT - 1), qy = q >> 5;
    int dv[4];
#pragma unroll
    for (int i = 0; i < 4; i++) {
        int k = tid * 4 + i;
        int kx = k & (RLAT - 1), ky = k >> 5;
        int dx = qx - kx, dy = qy - ky;
        dv[i] = dx * dx + dy * dy;
    }
    __shared__ int scount;
    int lo = 0, hi = 2 * 31 * 31;
    while (lo < hi) {
        int mid = (lo + hi) >> 1;
        if (tid == 0) scount = 0;
        __syncthreads();
        int c = 0;
#pragma unroll
        for (int i = 0; i < 4; i++) c += (dv[i] <= mid);
#pragma unroll
        for (int o = 16; o > 0; o >>= 1) c += __shfl_down_sync(0xffffffffu, c, o);
        if ((tid & 31) == 0) atomicAdd(&scount, c);
        __syncthreads();
        if (scount >= 21) hi = mid; else lo = mid + 1;
        __syncthreads();
    }
    if (tid == 0) {
        int n = 0;
        for (int k = 0; k < NLAT && n < 64; k++) {
            int kx = k & (RLAT - 1), ky = k >> 5;
            int dx = qx - kx, dy = qy - ky;
            if (dx * dx + dy * dy <= lo) kidx[q * 64 + (n++)] = k;
        }
        kcnt[q] = n;
    }
}

// ---------------------------------------------------------------------------
// Separable softmax factor: w[h][q][k] = exp(-s*0.5*(q/RQ-k/RK)^2) normalized
// over k (per-axis). Joint 2-D softmax == outer product of these factors.
// ---------------------------------------------------------------------------
template <int RQ, int RK>
__global__ void k_factor(const float* __restrict__ rv, float* __restrict__ w) {
    int h = blockIdx.x;
    int tid = threadIdx.x;
    if (tid >= RQ) return;
    float s = head_scale(rv[h]);
    float qp = (float)tid * (1.0f / RQ);
    float mind = 1e30f;
    for (int k = 0; k < RK; k++) {
        float d = qp - (float)k * (1.0f / RK);
        d = 0.5f * d * d;
        mind = fminf(mind, d);
    }
    float sum = 0.f;
    for (int k = 0; k < RK; k++) {
        float d = qp - (float)k * (1.0f / RK);
        d = 0.5f * d * d;
        sum += expf(s * (mind - d));
    }
    float inv = 1.0f / sum;
    for (int k = 0; k < RK; k++) {
        float d = qp - (float)k * (1.0f / RK);
        d = 0.5f * d * d;
        w[(h * RQ + tid) * RK + k] = expf(s * (mind - d)) * inv;
    }
}

// ---------------------------------------------------------------------------
// Encoder: out[b,n,c] = gelu(sum_j x[b,n,j]*W[j,c] + bias[c]),  K=3
// ---------------------------------------------------------------------------
__global__ void k_enc(const float* __restrict__ x, const float* __restrict__ w,
                      const float* __restrict__ bias, float* __restrict__ out) {
    int idx = blockIdx.x * 256 + threadIdx.x;
    int c = idx & (HID - 1);
    int bn = idx >> 7;
    float a = fmaf(x[bn * 3 + 0], w[c],
              fmaf(x[bn * 3 + 1], w[HID + c],
              fmaf(x[bn * 3 + 2], w[2 * HID + c], bias[c])));
    out[idx] = gelu_f(a);
}

// ---------------------------------------------------------------------------
// Rearrange per-head value weights [H][128][16] -> Wall[128][128]
// ---------------------------------------------------------------------------
__global__ void k_wrearr(const float* __restrict__ w, float* __restrict__ wall) {
    int idx = blockIdx.x * 256 + threadIdx.x;
    int j = idx >> 7, c = idx & (HID - 1);
    int h = c >> 4, vd = c & 15;
    wall[idx] = w[(h * HID + j) * VD + vd];
}

// ---------------------------------------------------------------------------
// 128-K GEMM with packed f32x2 FMA: C = act(A @ W + bias (+ addsrc))
// BM=64, BN=128, BK=32, 256 threads. Row-pair accumulators via fma.rn.f32x2.
// ---------------------------------------------------------------------------
__global__ void k_gemm128(const float* __restrict__ A, const float* __restrict__ W,
                          const float* __restrict__ bias, const float* __restrict__ addsrc,
                          float* __restrict__ C, int dogelu) {
    __shared__ float sA[32][66];     // [kk][row], even stride for 8B loads
    __shared__ float sB[32][128];
    int tid = threadIdx.x;
    int row0 = (tid >> 5) << 3;      // 8 rows per thread (4 pairs)
    int col0 = (tid & 31) << 2;      // 4 cols per thread
    size_t rbase = (size_t)blockIdx.x * 64;
    ull acc2[4][4];
#pragma unroll
    for (int p = 0; p < 4; p++)
#pragma unroll
        for (int j = 0; j < 4; j++) acc2[p][j] = 0ull;

    for (int k0 = 0; k0 < 128; k0 += 32) {
#pragma unroll
        for (int i = 0; i < 8; i++) {
            int idx = tid + i * 256;
            sA[idx & 31][idx >> 5] = A[(rbase + (idx >> 5)) * 128 + k0 + (idx & 31)];
        }
#pragma unroll
        for (int i = 0; i < 16; i++) {
            int idx = tid + i * 256;
            sB[idx >> 7][idx & 127] = W[(k0 + (idx >> 7)) * 128 + (idx & 127)];
        }
        __syncthreads();
#pragma unroll 4
        for (int kk = 0; kk < 32; kk++) {
            float4 bv = *reinterpret_cast<const float4*>(&sB[kk][col0]);
            ull bd[4];
            bd[0] = pack2(bv.x, bv.x);
            bd[1] = pack2(bv.y, bv.y);
            bd[2] = pack2(bv.z, bv.z);
            bd[3] = pack2(bv.w, bv.w);
            ull a01 = *reinterpret_cast<const ull*>(&sA[kk][row0 + 0]);
            ull a23 = *reinterpret_cast<const ull*>(&sA[kk][row0 + 2]);
            ull a45 = *reinterpret_cast<const ull*>(&sA[kk][row0 + 4]);
            ull a67 = *reinterpret_cast<const ull*>(&sA[kk][row0 + 6]);
#pragma unroll
            for (int j = 0; j < 4; j++) {
                ffma2(acc2[0][j], a01, bd[j]);
                ffma2(acc2[1][j], a23, bd[j]);
                ffma2(acc2[2][j], a45, bd[j]);
                ffma2(acc2[3][j], a67, bd[j]);
            }
        }
        __syncthreads();
    }
    float4 bsv = make_float4(0.f, 0.f, 0.f, 0.f);
    if (bias) bsv = *reinterpret_cast<const float4*>(&bias[col0]);
#pragma unroll
    for (int p = 0; p < 4; p++) {
#pragma unroll
        for (int half = 0; half < 2; half++) {
            size_t row = rbase + row0 + 2 * p + half;
            float4 r;
            if (half == 0) {
                r.x = lo32(acc2[p][0]); r.y = lo32(acc2[p][1]);
                r.z = lo32(acc2[p][2]); r.w = lo32(acc2[p][3]);
            } else {
                r.x = hi32(acc2[p][0]); r.y = hi32(acc2[p][1]);
                r.z = hi32(acc2[p][2]); r.w = hi32(acc2[p][3]);
            }
            r.x += bsv.x; r.y += bsv.y; r.z += bsv.z; r.w += bsv.w;
            if (addsrc) {
                float4 s = *reinterpret_cast<const float4*>(&addsrc[row * 128 + col0]);
                r.x += s.x; r.y += s.y; r.z += s.z; r.w += s.w;
            }
            if (dogelu) {
                r.x = gelu_f(r.x); r.y = gelu_f(r.y);
                r.z = gelu_f(r.z); r.w = gelu_f(r.w);
            }
            *reinterpret_cast<float4*>(&C[row * 128 + col0]) = r;
        }
    }
}

// ---------------------------------------------------------------------------
// Separable attention step 1 (contract ky):
//   T[b][qy][kx][c] = sum_ky w[h][qy][ky] * V[b][ky*RK+kx][c],  c = h*16+vd
// grid (RK/8, B, NH), block 256.
// ---------------------------------------------------------------------------
template <int RQ, int RK>
__global__ void k_sepY(const float* __restrict__ V, const float* __restrict__ w,
                       float* __restrict__ T) {
    constexpr int QPT = RQ / 8;
    __shared__ float sW[RQ * RK];
    __shared__ float sV[RK * 128];
    int tid = threadIdx.x;
    int kxc = blockIdx.x;
    int b = blockIdx.y, h = blockIdx.z;
    const float* wh = w + h * RQ * RK;
    for (int i = tid; i < RQ * RK; i += 256) sW[i] = wh[i];
    for (int i = tid; i < RK * 128; i += 256) {
        int ky = i >> 7, col = i & 127;
        int kx = kxc * 8 + (col >> 4), vd = col & 15;
        sV[i] = V[(((size_t)b * RK + ky) * RK + kx) * 128 + h * 16 + vd];
    }
    __syncthreads();
    int qy0 = (tid >> 5) * QPT, col0 = (tid & 31) * 4;
    float acc[QPT][4];
#pragma unroll
    for (int i = 0; i < QPT; i++)
#pragma unroll
        for (int j = 0; j < 4; j++) acc[i][j] = 0.f;
#pragma unroll 4
    for (int ky = 0; ky < RK; ky++) {
        float4 v = *reinterpret_cast<const float4*>(&sV[ky * 128 + col0]);
#pragma unroll
        for (int i = 0; i < QPT; i++) {
            float a = sW[(qy0 + i) * RK + ky];
            acc[i][0] = fmaf(a, v.x, acc[i][0]);
            acc[i][1] = fmaf(a, v.y, acc[i][1]);
            acc[i][2] = fmaf(a, v.z, acc[i][2]);
            acc[i][3] = fmaf(a, v.w, acc[i][3]);
        }
    }
    int kx = kxc * 8 + (col0 >> 4), vd0 = col0 & 15;
#pragma unroll
    for (int i = 0; i < QPT; i++) {
        float4 r = make_float4(acc[i][0], acc[i][1], acc[i][2], acc[i][3]);
        *reinterpret_cast<float4*>(
            &T[(((size_t)b * RQ + qy0 + i) * RK + kx) * 128 + h * 16 + vd0]) = r;
    }
}

// ---------------------------------------------------------------------------
// Separable attention step 2 (contract kx), fused gelu:
//   O[b][qy*RQ+qx][c] = gelu(sum_kx w[h][qx][kx] * T[b][qy][kx][c])
// grid (RQ(qy), B, NH), block 256.
// ---------------------------------------------------------------------------
template <int RQ, int RK>
__global__ void k_sepX(const float* __restrict__ T, const float* __restrict__ w,
                       float* __restrict__ O) {
    constexpr int QPT2 = RQ * 16 / 256;   // 2 (down) or 4 (up)
    __shared__ float sW[RQ * RK];
    __shared__ float sT[RK * 16];
    int tid = threadIdx.x;
    int qy = blockIdx.x;
    int b = blockIdx.y, h = blockIdx.z;
    const float* wh = w + h * RQ * RK;
    for (int i = tid; i < RQ * RK; i += 256) sW[i] = wh[i];
    for (int i = tid; i < RK * 16; i += 256) {
        int kx = i >> 4, vd = i & 15;
        sT[i] = T[(((size_t)b * RQ + qy) * RK + kx) * 128 + h * 16 + vd];
    }
    __syncthreads();
    int c = tid & 15;
    int qx0 = (tid >> 4) * QPT2;
    float acc[QPT2];
#pragma unroll
    for (int i = 0; i < QPT2; i++) acc[i] = 0.f;
#pragma unroll 4
    for (int kx = 0; kx < RK; kx++) {
        float v = sT[kx * 16 + c];
#pragma unroll
        for (int i = 0; i < QPT2; i++)
            acc[i] = fmaf(sW[(qx0 + i) * RK + kx], v, acc[i]);
    }
#pragma unroll
    for (int i = 0; i < QPT2; i++) {
        O[((size_t)b * RQ * RQ + qy * RQ + qx0 + i) * 128 + h * 16 + c] = gelu_f(acc[i]);
    }
}

// ---------------------------------------------------------------------------
// Sparse proc attention v2: grid (NLAT, 8), block 256 = 2 batches x 128 chans.
// Per-head probabilities in smem; fully coalesced 512B V row loads.
// ---------------------------------------------------------------------------
__global__ void k_procatt(const float* __restrict__ V, const float* __restrict__ rv,
                          const int* __restrict__ kidx, const int* __restrict__ kcnt,
                          float* __restrict__ out) {
    int q = blockIdx.x;
    int bg = blockIdx.y;
    int tid = threadIdx.x;
    __shared__ int   sidx[64];
    __shared__ float sdist[64];
    __shared__ float sp[NH][64];
    __shared__ float sscale[NH];
    __shared__ float ssum[NH];
    int cnt = kcnt[q];
    if (tid < cnt) {
        int k = kidx[q * 64 + tid];
        sidx[tid] = k;
        int qx = q & 31, qy = q >> 5;
        int kx = k & 31, ky = k >> 5;
        float dx = (qx - kx) * (1.0f / RLAT), dy = (qy - ky) * (1.0f / RLAT);
        sdist[tid] = 0.5f * (dx * dx + dy * dy);
    }
    if (tid < NH) sscale[tid] = head_scale(rv[tid]);
    __syncthreads();
    for (int jj = tid; jj < NH * 64; jj += 256) {
        int h = jj >> 6, j = jj & 63;
        if (j < cnt) sp[h][j] = expf(-sscale[h] * sdist[j]);
    }
    __syncthreads();
    if (tid < NH) {
        float s = 0.f;
        for (int j = 0; j < cnt; j++) s += sp[tid][j];
        ssum[tid] = s;
    }
    __syncthreads();
    int b = bg * 2 + (tid >> 7);
    int c = tid & 127;
    int h = c >> 4;
    const float* Vb = V + (size_t)b * NLAT * 128 + c;
    float acc = 0.f;
    int j = 0;
    for (; j + 4 <= cnt; j += 4) {
        float p0 = sp[h][j], p1 = sp[h][j + 1], p2 = sp[h][j + 2], p3 = sp[h][j + 3];
        int i0 = sidx[j], i1 = sidx[j + 1], i2 = sidx[j + 2], i3 = sidx[j + 3];
        float v0 = Vb[(size_t)i0 * 128];
        float v1 = Vb[(size_t)i1 * 128];
        float v2 = Vb[(size_t)i2 * 128];
        float v3 = Vb[(size_t)i3 * 128];
        acc = fmaf(p0, v0, acc);
        acc = fmaf(p1, v1, acc);
        acc = fmaf(p2, v2, acc);
        acc = fmaf(p3, v3, acc);
    }
    for (; j < cnt; j++) acc = fmaf(sp[h][j], Vb[(size_t)sidx[j] * 128], acc);
    out[((size_t)b * NLAT + q) * 128 + c] = gelu_f(acc / ssum[h]);
}

// ---------------------------------------------------------------------------
// Final projection 128 -> 1: warp per row
// ---------------------------------------------------------------------------
__global__ void k_dec2(const float* __restrict__ H, const float* __restrict__ w,
                       const float* __restrict__ b0, float* __restrict__ out) {
    int row = blockIdx.x * 8 + (threadIdx.x >> 5);
    int lane = threadIdx.x & 31;
    const float4 h4 = reinterpret_cast<const float4*>(H + (size_t)row * 128)[lane];
    const float4 w4 = reinterpret_cast<const float4*>(w)[lane];
    float s = h4.x * w4.x + h4.y * w4.y + h4.z * w4.z + h4.w * w4.w;
#pragma unroll
    for (int o = 16; o > 0; o >>= 1) s += __shfl_down_sync(0xffffffffu, s, o);
    if (lane == 0) out[row] = s + b0[0];
}

// ---------------------------------------------------------------------------
// Launcher
// ---------------------------------------------------------------------------
extern "C" void kernel_launch(void* const* d_in, const int* in_sizes, int n_in,
                              void* d_out, int out_size) {
    const float* x        = (const float*)d_in[0];
    const float* en_w     = (const float*)d_in[1];
    const float* en_b     = (const float*)d_in[2];
    const float* down_r   = (const float*)d_in[3];
    const float* down_w   = (const float*)d_in[4];
    const float* pa_r     = (const float*)d_in[5];
    const float* pa_w     = (const float*)d_in[6];
    const float* mlp1_w   = (const float*)d_in[7];
    const float* mlp1_b   = (const float*)d_in[8];
    const float* mlp2_w   = (const float*)d_in[9];
    const float* mlp2_b   = (const float*)d_in[10];
    const float* res_w    = (const float*)d_in[11];
    const float* res_b    = (const float*)d_in[12];
    const float* up_r     = (const float*)d_in[13];
    const float* up_w     = (const float*)d_in[14];
    const float* de1_w    = (const float*)d_in[15];
    const float* de1_b    = (const float*)d_in[16];
    const float* de2_w    = (const float*)d_in[17];
    const float* de2_b    = (const float*)d_in[18];
    float* out = (float*)d_out;

    float *h0, *val, *hup, *hA, *hB, *pa, *t1, *t2, *wall, *wdn, *wup;
    int *kidx, *kcnt;
    cudaGetSymbolAddress((void**)&h0,   g_h0);
    cudaGetSymbolAddress((void**)&val,  g_val);
    cudaGetSymbolAddress((void**)&hup,  g_hup);
    cudaGetSymbolAddress((void**)&hA,   g_hA);
    cudaGetSymbolAddress((void**)&hB,   g_hB);
    cudaGetSymbolAddress((void**)&pa,   g_pa);
    cudaGetSymbolAddress((void**)&t1,   g_t1);
    cudaGetSymbolAddress((void**)&t2,   g_t2);
    cudaGetSymbolAddress((void**)&wall, g_wall);
    cudaGetSymbolAddress((void**)&wdn,  g_wdn);
    cudaGetSymbolAddress((void**)&wup,  g_wup);
    cudaGetSymbolAddress((void**)&kidx, g_kidx);
    cudaGetSymbolAddress((void**)&kcnt, g_kcnt);

    const int M_IN  = BATCH * NIN;   // 65536
    const int M_LAT = BATCH * NLAT;  // 16384

    // precomputes
    k_knn<<<NLAT, 256>>>(kidx, kcnt);
    k_factor<RLAT, RIN><<<NH, 64>>>(down_r, wdn);   // down: 32q x 64k per axis
    k_factor<RIN, RLAT><<<NH, 64>>>(up_r, wup);     // up:   64q x 32k per axis

    // encoder
    k_enc<<<(BATCH * NIN * HID) / 256, 256>>>(x, en_w, en_b, h0);

    // ---- down pos-attention (separable) ----
    k_wrearr<<<64, 256>>>(down_w, wall);
    k_gemm128<<<M_IN / 64, 256>>>(h0, wall, nullptr, nullptr, val, 0);
    {
        dim3 g1(RIN / 8, BATCH, NH);    // contract ky over 64 keys
        k_sepY<RLAT, RIN><<<g1, 256>>>(val, wdn, h0);   // T into h0 (free now)
        dim3 g2(RLAT, BATCH, NH);
        k_sepX<RLAT, RIN><<<g2, 256>>>(h0, wdn, hA);
    }

    // ---- processor blocks ----
    float* hin = hA;
    float* hout = hB;
    for (int i = 0; i < 3; i++) {
        k_wrearr<<<64, 256>>>(pa_w + (size_t)i * NH * HID * VD, wall);
        k_gemm128<<<M_LAT / 64, 256>>>(hin, wall, nullptr, nullptr, val, 0);
        {
            dim3 g(NLAT, 8);
            k_procatt<<<g, 256>>>(val, pa_r + i * NH, kidx, kcnt, pa);
        }
        k_gemm128<<<M_LAT / 64, 256>>>(pa, mlp1_w + (size_t)i * HID * HID,
                                       mlp1_b + i * HID, nullptr, t1, 1);
        k_gemm128<<<M_LAT / 64, 256>>>(t1, mlp2_w + (size_t)i * HID * HID,
                                       mlp2_b + i * HID, nullptr, t2, 0);
        k_gemm128<<<M_LAT / 64, 256>>>(hin, res_w + (size_t)i * HID * HID,
                                       res_b + i * HID, t2, hout, 1);
        float* tmp = hin; hin = hout; hout = tmp;
    }

    // ---- up pos-attention (separable) ----
    k_wrearr<<<64, 256>>>(up_w, wall);
    k_gemm128<<<M_LAT / 64, 256>>>(hin, wall, nullptr, nullptr, val, 0);
    {
        dim3 g1(RLAT / 8, BATCH, NH);   // contract ky over 32 keys
        k_sepY<RIN, RLAT><<<g1, 256>>>(val, wup, h0);   // T into h0
        dim3 g2(RIN, BATCH, NH);
        k_sepX<RIN, RLAT><<<g2, 256>>>(h0, wup, hup);
    }

    // ---- decoder ----
    k_gemm128<<<M_IN / 64, 256>>>(hup, de1_w, de1_b, nullptr, h0, 1);
    k_dec2<<<M_IN / 8, 256>>>(h0, de2_w, de2_b, out);
}

// round 3
// speedup vs baseline: 3.5735x; 1.0681x over previous
#include <cuda_runtime.h>
#include <cuda_bf16.h>
#include <math.h>

// ---------------------------------------------------------------------------
// Problem constants
// ---------------------------------------------------------------------------
#define BATCH   16
#define NH      8
#define HID     128
#define VD      16
#define RIN     64          // input res (64x64)
#define RLAT    32          // latent res (32x32)
#define NIN     (RIN*RIN)   // 4096
#define NLAT    (RLAT*RLAT) // 1024
#define PI_F    3.14159265358979323846f

typedef unsigned long long ull;

// ---------------------------------------------------------------------------
// Scratch buffers (static device globals -- no allocation anywhere)
// ---------------------------------------------------------------------------
__device__ float g_h0 [BATCH*NIN*HID];   // T scratch for separable attention
__device__ float g_val[BATCH*NIN*HID];   // value projection (max size)
__device__ float g_hup[BATCH*NIN*HID];   // up-attention output
__device__ float g_hA [BATCH*NLAT*HID];
__device__ float g_hB [BATCH*NLAT*HID];
__device__ float g_pa [BATCH*NLAT*HID];
__device__ float g_t1 [BATCH*NLAT*HID];
__device__ float g_wdn[NH*RLAT*RIN];     // separable factors: down (32q x 64k)
__device__ float g_wup[NH*RIN*RLAT];     // separable factors: up   (64q x 32k)
__device__ int   g_kidx[NLAT*64];
__device__ int   g_kcnt[NLAT];

// ---------------------------------------------------------------------------
// Helpers
// ---------------------------------------------------------------------------
// gelu(x) = 0.5*x*(1+tanh(y)), y = sqrt(2/pi)*(x+0.044715x^3)
//         = x * sigmoid(2y)  (exact algebraic identity)
__device__ __forceinline__ float gelu_f(float x) {
    const float c = 0.7978845608028654f;
    float y = c * fmaf(0.044715f * x, x * x, x);
    return x / (1.0f + __expf(-2.0f * y));
}

__device__ __forceinline__ float head_scale(float r) {
    return tanf(0.25f * PI_F * (1.0f - 1e-7f) * (1.0f + sinf(r)));
}

__device__ __forceinline__ ull pack2(float x, float y) {
    ull r;
    asm("mov.b64 %0, {%1, %2};" : "=l"(r) : "f"(x), "f"(y));
    return r;
}
__device__ __forceinline__ void ffma2(ull& d, ull a, ull b) {
    asm("fma.rn.f32x2 %0, %1, %2, %3;" : "=l"(d) : "l"(a), "l"(b), "l"(d));
}
__device__ __forceinline__ float lo32(ull v) {
    return __int_as_float((int)(unsigned)(v & 0xffffffffull));
}
__device__ __forceinline__ float hi32(ull v) {
    return __int_as_float((int)(unsigned)(v >> 32));
}

// ---------------------------------------------------------------------------
// kNN precompute for proc locality mask (2nd percentile => keep dv <= dv20)
// ---------------------------------------------------------------------------
__global__ void k_knn(int* __restrict__ kidx, int* __restrict__ kcnt) {
    int q = blockIdx.x;
    int tid = threadIdx.x;                  // 256 threads, 4 keys each
    int qx = q & (RLAT - 1), qy = q >> 5;
    int dv[4];
#pragma unroll
    for (int i = 0; i < 4; i++) {
        int k = tid * 4 + i;
        int kx = k & (RLAT - 1), ky = k >> 5;
        int dx = qx - kx, dy = qy - ky;
        dv[i] = dx * dx + dy * dy;
    }
    __shared__ int scount;
    int lo = 0, hi = 2 * 31 * 31;
    while (lo < hi) {
        int mid = (lo + hi) >> 1;
        if (tid == 0) scount = 0;
        __syncthreads();
        int c = 0;
#pragma unroll
        for (int i = 0; i < 4; i++) c += (dv[i] <= mid);
#pragma unroll
        for (int o = 16; o > 0; o >>= 1) c += __shfl_down_sync(0xffffffffu, c, o);
        if ((tid & 31) == 0) atomicAdd(&scount, c);
        __syncthreads();
        if (scount >= 21) hi = mid; else lo = mid + 1;
        __syncthreads();
    }
    if (tid == 0) {
        int n = 0;
        for (int k = 0; k < NLAT && n < 64; k++) {
            int kx = k & (RLAT - 1), ky = k >> 5;
            int dx = qx - kx, dy = qy - ky;
            if (dx * dx + dy * dy <= lo) kidx[q * 64 + (n++)] = k;
        }
        kcnt[q] = n;
    }
}

// ---------------------------------------------------------------------------
// Separable softmax factor (per-axis normalized; outer product == joint sm)
// ---------------------------------------------------------------------------
template <int RQ, int RK>
__global__ void k_factor(const float* __restrict__ rv, float* __restrict__ w) {
    int h = blockIdx.x;
    int tid = threadIdx.x;
    if (tid >= RQ) return;
    float s = head_scale(rv[h]);
    float qp = (float)tid * (1.0f / RQ);
    float mind = 1e30f;
    for (int k = 0; k < RK; k++) {
        float d = qp - (float)k * (1.0f / RK);
        d = 0.5f * d * d;
        mind = fminf(mind, d);
    }
    float sum = 0.f;
    for (int k = 0; k < RK; k++) {
        float d = qp - (float)k * (1.0f / RK);
        d = 0.5f * d * d;
        sum += expf(s * (mind - d));
    }
    float inv = 1.0f / sum;
    for (int k = 0; k < RK; k++) {
        float d = qp - (float)k * (1.0f / RK);
        d = 0.5f * d * d;
        w[(h * RQ + tid) * RK + k] = expf(s * (mind - d)) * inv;
    }
}

// ---------------------------------------------------------------------------
// Unified 128-K GEMM, BM=64 BN=128 BK=32, 256 threads, packed f32x2 FMA.
// Template modes:
//   AENC : A-tile computed on the fly as gelu(x @ enW + enb)  (encoder fusion)
//   BRE  : B loaded from per-head value-weight layout [H][128][16]
//   DUAL : accumulate A@W + A2@W2 (K=256 effective); bias2 added
//   DOGELU: gelu on output
//   DEC  : decoder epilogue -- dot rows with d2w, warp-reduce, write scalar
// ---------------------------------------------------------------------------
template <int AENC, int BRE, int DUAL, int DOGELU, int DEC>
__global__ void k_gemm(const float* __restrict__ A,  const float* __restrict__ W,
                       const float* __restrict__ A2, const float* __restrict__ W2,
                       const float* __restrict__ bias, const float* __restrict__ bias2,
                       const float* __restrict__ x, const float* __restrict__ enw,
                       const float* __restrict__ enb,
                       const float* __restrict__ d2w, const float* __restrict__ d2b,
                       float* __restrict__ C) {
    __shared__ float sA[32][66];
    __shared__ float sB[32][128];
    int tid = threadIdx.x;
    int row0 = (tid >> 5) << 3;
    int col0 = (tid & 31) << 2;
    size_t rbase = (size_t)blockIdx.x * 64;
    ull acc2[4][4];
#pragma unroll
    for (int p = 0; p < 4; p++)
#pragma unroll
        for (int j = 0; j < 4; j++) acc2[p][j] = 0ull;

    const int NPASS = DUAL ? 2 : 1;
#pragma unroll
    for (int pass = 0; pass < NPASS; pass++) {
        const float* Ap = (DUAL && pass) ? A2 : A;
        const float* Wp = (DUAL && pass) ? W2 : W;
        for (int k0 = 0; k0 < 128; k0 += 32) {
            if (AENC) {
#pragma unroll
                for (int i = 0; i < 8; i++) {
                    int idx = tid + i * 256;
                    int r = idx >> 5, c = k0 + (idx & 31);
                    size_t grow = rbase + r;
                    float a = fmaf(x[grow * 3 + 0], enw[c],
                              fmaf(x[grow * 3 + 1], enw[HID + c],
                              fmaf(x[grow * 3 + 2], enw[2 * HID + c], enb[c])));
                    sA[idx & 31][r] = gelu_f(a);
                }
            } else {
#pragma unroll
                for (int i = 0; i < 8; i++) {
                    int idx = tid + i * 256;
                    sA[idx & 31][idx >> 5] = Ap[(rbase + (idx >> 5)) * 128 + k0 + (idx & 31)];
                }
            }
#pragma unroll
            for (int i = 0; i < 16; i++) {
                int idx = tid + i * 256;
                int kk = idx >> 7, c = idx & 127;
                float wv;
                if (BRE) {
                    int h = c >> 4, vd = c & 15;
                    wv = Wp[((h * HID) + (k0 + kk)) * VD + vd];
                } else {
                    wv = Wp[(k0 + kk) * 128 + c];
                }
                sB[kk][c] = wv;
            }
            __syncthreads();
#pragma unroll 4
            for (int kk = 0; kk < 32; kk++) {
                float4 bv = *reinterpret_cast<const float4*>(&sB[kk][col0]);
                ull bd[4];
                bd[0] = pack2(bv.x, bv.x);
                bd[1] = pack2(bv.y, bv.y);
                bd[2] = pack2(bv.z, bv.z);
                bd[3] = pack2(bv.w, bv.w);
                ull a01 = *reinterpret_cast<const ull*>(&sA[kk][row0 + 0]);
                ull a23 = *reinterpret_cast<const ull*>(&sA[kk][row0 + 2]);
                ull a45 = *reinterpret_cast<const ull*>(&sA[kk][row0 + 4]);
                ull a67 = *reinterpret_cast<const ull*>(&sA[kk][row0 + 6]);
#pragma unroll
                for (int j = 0; j < 4; j++) {
                    ffma2(acc2[0][j], a01, bd[j]);
                    ffma2(acc2[1][j], a23, bd[j]);
                    ffma2(acc2[2][j], a45, bd[j]);
                    ffma2(acc2[3][j], a67, bd[j]);
                }
            }
            __syncthreads();
        }
    }

    float4 bsv = make_float4(0.f, 0.f, 0.f, 0.f);
    if (bias) {
        float4 b1 = *reinterpret_cast<const float4*>(&bias[col0]);
        bsv.x += b1.x; bsv.y += b1.y; bsv.z += b1.z; bsv.w += b1.w;
    }
    if (DUAL && bias2) {
        float4 b2 = *reinterpret_cast<const float4*>(&bias2[col0]);
        bsv.x += b2.x; bsv.y += b2.y; bsv.z += b2.z; bsv.w += b2.w;
    }

    float4 dwv = make_float4(0.f, 0.f, 0.f, 0.f);
    float dbb = 0.f;
    if (DEC) {
        dwv = *reinterpret_cast<const float4*>(&d2w[col0]);
        dbb = d2b[0];
    }

#pragma unroll
    for (int p = 0; p < 4; p++) {
#pragma unroll
        for (int half = 0; half < 2; half++) {
            size_t row = rbase + row0 + 2 * p + half;
            float4 r;
            if (half == 0) {
                r.x = lo32(acc2[p][0]); r.y = lo32(acc2[p][1]);
                r.z = lo32(acc2[p][2]); r.w = lo32(acc2[p][3]);
            } else {
                r.x = hi32(acc2[p][0]); r.y = hi32(acc2[p][1]);
                r.z = hi32(acc2[p][2]); r.w = hi32(acc2[p][3]);
            }
            r.x += bsv.x; r.y += bsv.y; r.z += bsv.z; r.w += bsv.w;
            if (DOGELU) {
                r.x = gelu_f(r.x); r.y = gelu_f(r.y);
                r.z = gelu_f(r.z); r.w = gelu_f(r.w);
            }
            if (DEC) {
                float part = r.x * dwv.x + r.y * dwv.y + r.z * dwv.z + r.w * dwv.w;
#pragma unroll
                for (int o = 16; o > 0; o >>= 1)
                    part += __shfl_down_sync(0xffffffffu, part, o);
                if ((tid & 31) == 0) C[row] = part + dbb;
            } else {
                *reinterpret_cast<float4*>(&C[row * 128 + col0]) = r;
            }
        }
    }
}

// ---------------------------------------------------------------------------
// Separable attention step 1 (contract ky):
//   T[b][qy][kx][c] = sum_ky w[h][qy][ky] * V[b][ky*RK+kx][c]
// ---------------------------------------------------------------------------
template <int RQ, int RK>
__global__ void k_sepY(const float* __restrict__ V, const float* __restrict__ w,
                       float* __restrict__ T) {
    constexpr int QPT = RQ / 8;
    __shared__ float sW[RQ * RK];
    __shared__ float sV[RK * 128];
    int tid = threadIdx.x;
    int kxc = blockIdx.x;
    int b = blockIdx.y, h = blockIdx.z;
    const float* wh = w + h * RQ * RK;
    for (int i = tid; i < RQ * RK; i += 256) sW[i] = wh[i];
    for (int i = tid; i < RK * 128; i += 256) {
        int ky = i >> 7, col = i & 127;
        int kx = kxc * 8 + (col >> 4), vd = col & 15;
        sV[i] = V[(((size_t)b * RK + ky) * RK + kx) * 128 + h * 16 + vd];
    }
    __syncthreads();
    int qy0 = (tid >> 5) * QPT, col0 = (tid & 31) * 4;
    float acc[QPT][4];
#pragma unroll
    for (int i = 0; i < QPT; i++)
#pragma unroll
        for (int j = 0; j < 4; j++) acc[i][j] = 0.f;
#pragma unroll 4
    for (int ky = 0; ky < RK; ky++) {
        float4 v = *reinterpret_cast<const float4*>(&sV[ky * 128 + col0]);
#pragma unroll
        for (int i = 0; i < QPT; i++) {
            float a = sW[(qy0 + i) * RK + ky];
            acc[i][0] = fmaf(a, v.x, acc[i][0]);
            acc[i][1] = fmaf(a, v.y, acc[i][1]);
            acc[i][2] = fmaf(a, v.z, acc[i][2]);
            acc[i][3] = fmaf(a, v.w, acc[i][3]);
        }
    }
    int kx = kxc * 8 + (col0 >> 4), vd0 = col0 & 15;
#pragma unroll
    for (int i = 0; i < QPT; i++) {
        float4 r = make_float4(acc[i][0], acc[i][1], acc[i][2], acc[i][3]);
        *reinterpret_cast<float4*>(
            &T[(((size_t)b * RQ + qy0 + i) * RK + kx) * 128 + h * 16 + vd0]) = r;
    }
}

// ---------------------------------------------------------------------------
// Separable attention step 2 (contract kx), fused gelu
// ---------------------------------------------------------------------------
template <int RQ, int RK>
__global__ void k_sepX(const float* __restrict__ T, const float* __restrict__ w,
                       float* __restrict__ O) {
    constexpr int QPT2 = RQ * 16 / 256;
    __shared__ float sW[RQ * RK];
    __shared__ float sT[RK * 16];
    int tid = threadIdx.x;
    int qy = blockIdx.x;
    int b = blockIdx.y, h = blockIdx.z;
    const float* wh = w + h * RQ * RK;
    for (int i = tid; i < RQ * RK; i += 256) sW[i] = wh[i];
    for (int i = tid; i < RK * 16; i += 256) {
        int kx = i >> 4, vd = i & 15;
        sT[i] = T[(((size_t)b * RQ + qy) * RK + kx) * 128 + h * 16 + vd];
    }
    __syncthreads();
    int c = tid & 15;
    int qx0 = (tid >> 4) * QPT2;
    float acc[QPT2];
#pragma unroll
    for (int i = 0; i < QPT2; i++) acc[i] = 0.f;
#pragma unroll 4
    for (int kx = 0; kx < RK; kx++) {
        float v = sT[kx * 16 + c];
#pragma unroll
        for (int i = 0; i < QPT2; i++)
            acc[i] = fmaf(sW[(qx0 + i) * RK + kx], v, acc[i]);
    }
#pragma unroll
    for (int i = 0; i < QPT2; i++) {
        O[((size_t)b * RQ * RQ + qy * RQ + qx0 + i) * 128 + h * 16 + c] = gelu_f(acc[i]);
    }
}

// ---------------------------------------------------------------------------
// Sparse proc attention: grid (NLAT, 8), block 256 = 2 batches x 128 chans
// ---------------------------------------------------------------------------
__global__ void k_procatt(const float* __restrict__ V, const float* __restrict__ rv,
                          const int* __restrict__ kidx, const int* __restrict__ kcnt,
                          float* __restrict__ out) {
    int q = blockIdx.x;
    int bg = blockIdx.y;
    int tid = threadIdx.x;
    __shared__ int   sidx[64];
    __shared__ float sdist[64];
    __shared__ float sp[NH][64];
    __shared__ float sscale[NH];
    __shared__ float ssum[NH];
    int cnt = kcnt[q];
    if (tid < cnt) {
        int k = kidx[q * 64 + tid];
        sidx[tid] = k;
        int qx = q & 31, qy = q >> 5;
        int kx = k & 31, ky = k >> 5;
        float dx = (qx - kx) * (1.0f / RLAT), dy = (qy - ky) * (1.0f / RLAT);
        sdist[tid] = 0.5f * (dx * dx + dy * dy);
    }
    if (tid < NH) sscale[tid] = head_scale(rv[tid]);
    __syncthreads();
    for (int jj = tid; jj < NH * 64; jj += 256) {
        int h = jj >> 6, j = jj & 63;
        if (j < cnt) sp[h][j] = expf(-sscale[h] * sdist[j]);
    }
    __syncthreads();
    if (tid < NH) {
        float s = 0.f;
        for (int j = 0; j < cnt; j++) s += sp[tid][j];
        ssum[tid] = s;
    }
    __syncthreads();
    int b = bg * 2 + (tid >> 7);
    int c = tid & 127;
    int h = c >> 4;
    const float* Vb = V + (size_t)b * NLAT * 128 + c;
    float acc = 0.f;
    int j = 0;
    for (; j + 4 <= cnt; j += 4) {
        float p0 = sp[h][j], p1 = sp[h][j + 1], p2 = sp[h][j + 2], p3 = sp[h][j + 3];
        int i0 = sidx[j], i1 = sidx[j + 1], i2 = sidx[j + 2], i3 = sidx[j + 3];
        float v0 = Vb[(size_t)i0 * 128];
        float v1 = Vb[(size_t)i1 * 128];
        float v2 = Vb[(size_t)i2 * 128];
        float v3 = Vb[(size_t)i3 * 128];
        acc = fmaf(p0, v0, acc);
        acc = fmaf(p1, v1, acc);
        acc = fmaf(p2, v2, acc);
        acc = fmaf(p3, v3, acc);
    }
    for (; j < cnt; j++) acc = fmaf(sp[h][j], Vb[(size_t)sidx[j] * 128], acc);
    out[((size_t)b * NLAT + q) * 128 + c] = gelu_f(acc / ssum[h]);
}

// ---------------------------------------------------------------------------
// Launcher
// ---------------------------------------------------------------------------
extern "C" void kernel_launch(void* const* d_in, const int* in_sizes, int n_in,
                              void* d_out, int out_size) {
    const float* x        = (const float*)d_in[0];
    const float* en_w     = (const float*)d_in[1];
    const float* en_b     = (const float*)d_in[2];
    const float* down_r   = (const float*)d_in[3];
    const float* down_w   = (const float*)d_in[4];
    const float* pa_r     = (const float*)d_in[5];
    const float* pa_w     = (const float*)d_in[6];
    const float* mlp1_w   = (const float*)d_in[7];
    const float* mlp1_b   = (const float*)d_in[8];
    const float* mlp2_w   = (const float*)d_in[9];
    const float* mlp2_b   = (const float*)d_in[10];
    const float* res_w    = (const float*)d_in[11];
    const float* res_b    = (const float*)d_in[12];
    const float* up_r     = (const float*)d_in[13];
    const float* up_w     = (const float*)d_in[14];
    const float* de1_w    = (const float*)d_in[15];
    const float* de1_b    = (const float*)d_in[16];
    const float* de2_w    = (const float*)d_in[17];
    const float* de2_b    = (const float*)d_in[18];
    float* out = (float*)d_out;

    float *h0, *val, *hup, *hA, *hB, *pa, *t1, *wdn, *wup;
    int *kidx, *kcnt;
    cudaGetSymbolAddress((void**)&h0,   g_h0);
    cudaGetSymbolAddress((void**)&val,  g_val);
    cudaGetSymbolAddress((void**)&hup,  g_hup);
    cudaGetSymbolAddress((void**)&hA,   g_hA);
    cudaGetSymbolAddress((void**)&hB,   g_hB);
    cudaGetSymbolAddress((void**)&pa,   g_pa);
    cudaGetSymbolAddress((void**)&t1,   g_t1);
    cudaGetSymbolAddress((void**)&wdn,  g_wdn);
    cudaGetSymbolAddress((void**)&wup,  g_wup);
    cudaGetSymbolAddress((void**)&kidx, g_kidx);
    cudaGetSymbolAddress((void**)&kcnt, g_kcnt);

    const int M_IN  = BATCH * NIN;   // 65536
    const int M_LAT = BATCH * NLAT;  // 16384

    // precomputes
    k_knn<<<NLAT, 256>>>(kidx, kcnt);
    k_factor<RLAT, RIN><<<NH, 64>>>(down_r, wdn);
    k_factor<RIN, RLAT><<<NH, 64>>>(up_r, wup);

    // ---- down: fused encoder + value GEMM, then separable attention ----
    k_gemm<1, 1, 0, 0, 0><<<M_IN / 64, 256>>>(
        nullptr, down_w, nullptr, nullptr, nullptr, nullptr,
        x, en_w, en_b, nullptr, nullptr, val);
    {
        dim3 g1(RIN / 8, BATCH, NH);
        k_sepY<RLAT, RIN><<<g1, 256>>>(val, wdn, h0);
        dim3 g2(RLAT, BATCH, NH);
        k_sepX<RLAT, RIN><<<g2, 256>>>(h0, wdn, hA);
    }

    // ---- processor blocks ----
    float* hin = hA;
    float* hout = hB;
    for (int i = 0; i < 3; i++) {
        // value projection (head-layout weights loaded directly)
        k_gemm<0, 1, 0, 0, 0><<<M_LAT / 64, 256>>>(
            hin, pa_w + (size_t)i * NH * HID * VD, nullptr, nullptr,
            nullptr, nullptr, nullptr, nullptr, nullptr, nullptr, nullptr, val);
        {
            dim3 g(NLAT, 8);
            k_procatt<<<g, 256>>>(val, pa_r + i * NH, kidx, kcnt, pa);
        }
        // mlp1: gelu(pa @ W1 + b1)
        k_gemm<0, 0, 0, 1, 0><<<M_LAT / 64, 256>>>(
            pa, mlp1_w + (size_t)i * HID * HID, nullptr, nullptr,
            mlp1_b + i * HID, nullptr, nullptr, nullptr, nullptr, nullptr, nullptr, t1);
        // fused mlp2 + residual: gelu(t1@W2 + b2 + hin@Wres + bres)
        k_gemm<0, 0, 1, 1, 0><<<M_LAT / 64, 256>>>(
            t1, mlp2_w + (size_t)i * HID * HID,
            hin, res_w + (size_t)i * HID * HID,
            mlp2_b + i * HID, res_b + i * HID,
            nullptr, nullptr, nullptr, nullptr, nullptr, hout);
        float* tmp = hin; hin = hout; hout = tmp;
    }

    // ---- up: value GEMM + separable attention ----
    k_gemm<0, 1, 0, 0, 0><<<M_LAT / 64, 256>>>(
        hin, up_w, nullptr, nullptr, nullptr, nullptr,
        nullptr, nullptr, nullptr, nullptr, nullptr, val);
    {
        dim3 g1(RLAT / 8, BATCH, NH);
        k_sepY<RIN, RLAT><<<g1, 256>>>(val, wup, h0);
        dim3 g2(RIN, BATCH, NH);
        k_sepX<RIN, RLAT><<<g2, 256>>>(h0, wup, hup);
    }

    // ---- fused decoder: out = gelu(hup @ de1W + de1b) @ de2W + de2b ----
    k_gemm<0, 0, 0, 1, 1><<<M_IN / 64, 256>>>(
        hup, de1_w, nullptr, nullptr, de1_b, nullptr,
        nullptr, nullptr, nullptr, de2_w, de2_b, out);
}

// round 4
// speedup vs baseline: 4.2645x; 1.1934x over previous
#include <cuda_runtime.h>
#include <cuda_bf16.h>
#include <math.h>

// ---------------------------------------------------------------------------
// Problem constants
// ---------------------------------------------------------------------------
#define BATCH   16
#define NH      8
#define HID     128
#define VD      16
#define RIN     64
#define RLAT    32
#define NIN     (RIN*RIN)   // 4096
#define NLAT    (RLAT*RLAT) // 1024
#define PI_F    3.14159265358979323846f

#define NWMAT   15
#define GEMM_SMEM (4*128*136*2)   // sAh,sAl,sBh,sBl : 139264 bytes

// ---------------------------------------------------------------------------
// Scratch buffers (static device globals -- no allocation anywhere)
// ---------------------------------------------------------------------------
__device__ float g_h0 [BATCH*NIN*HID];
__device__ float g_val[BATCH*NIN*HID];
__device__ float g_hup[BATCH*NIN*HID];
__device__ float g_hA [BATCH*NLAT*HID];
__device__ float g_hB [BATCH*NLAT*HID];
__device__ float g_pa [BATCH*NLAT*HID];
__device__ float g_t1 [BATCH*NLAT*HID];
__device__ float g_wdn[NH*RLAT*RIN];
__device__ float g_wup[NH*RIN*RLAT];
__device__ int   g_kidx[NLAT*64];
__device__ int   g_kcnt[NLAT];
__device__ __align__(16) __nv_bfloat16 g_bwh[NWMAT*HID*HID];  // pretransposed [n][k] hi
__device__ __align__(16) __nv_bfloat16 g_bwl[NWMAT*HID*HID];  // lo

// ---------------------------------------------------------------------------
// Helpers
// ---------------------------------------------------------------------------
__device__ __forceinline__ float gelu_f(float x) {
    const float c = 0.7978845608028654f;
    float y = c * fmaf(0.044715f * x, x * x, x);
    return x / (1.0f + __expf(-2.0f * y));
}

__device__ __forceinline__ float head_scale(float r) {
    return tanf(0.25f * PI_F * (1.0f - 1e-7f) * (1.0f + sinf(r)));
}

__device__ __forceinline__ void split_bf(float v, __nv_bfloat16& h, __nv_bfloat16& l) {
    h = __float2bfloat16(v);
    l = __float2bfloat16(v - __bfloat162float(h));
}

__device__ __forceinline__ void mma_bf16(float* d,
        unsigned a0, unsigned a1, unsigned a2, unsigned a3,
        unsigned b0, unsigned b1) {
    asm volatile(
        "mma.sync.aligned.m16n8k16.row.col.f32.bf16.bf16.f32 "
        "{%0,%1,%2,%3}, {%4,%5,%6,%7}, {%8,%9}, {%0,%1,%2,%3};"
        : "+f"(d[0]), "+f"(d[1]), "+f"(d[2]), "+f"(d[3])
        : "r"(a0), "r"(a1), "r"(a2), "r"(a3), "r"(b0), "r"(b1));
}

// ---------------------------------------------------------------------------
// Weight prep: convert 15 [128x128] weight matrices (some in per-head layout)
// to bf16 hi/lo, transposed to [n][k] for fragment-friendly loads.
// ---------------------------------------------------------------------------
struct BWList { const float* w[NWMAT]; unsigned bre_mask; };

__global__ void k_prepB(BWList L, __nv_bfloat16* __restrict__ outh,
                        __nv_bfloat16* __restrict__ outl) {
    int mat = blockIdx.y;
    const float* w = L.w[mat];
    int bre = (L.bre_mask >> mat) & 1;
    int idx = blockIdx.x * 256 + threadIdx.x;   // 16384 per matrix
    int k = idx >> 7, n = idx & 127;
    float v;
    if (bre) {
        int h = n >> 4, vd = n & 15;
        v = w[((size_t)h * HID + k) * VD + vd];
    } else {
        v = w[k * HID + n];
    }
    __nv_bfloat16 hi, lo;
    split_bf(v, hi, lo);
    size_t o = (size_t)mat * HID * HID + n * HID + k;
    outh[o] = hi;
    outl[o] = lo;
}

// ---------------------------------------------------------------------------
// kNN precompute for proc locality mask
// ---------------------------------------------------------------------------
__global__ void k_knn(int* __restrict__ kidx, int* __restrict__ kcnt) {
    int q = blockIdx.x;
    int tid = threadIdx.x;
    int qx = q & (RLAT - 1), qy = q >> 5;
    int dv[4];
#pragma unroll
    for (int i = 0; i < 4; i++) {
        int k = tid * 4 + i;
        int kx = k & (RLAT - 1), ky = k >> 5;
        int dx = qx - kx, dy = qy - ky;
        dv[i] = dx * dx + dy * dy;
    }
    __shared__ int scount;
    int lo = 0, hi = 2 * 31 * 31;
    while (lo < hi) {
        int mid = (lo + hi) >> 1;
        if (tid == 0) scount = 0;
        __syncthreads();
        int c = 0;
#pragma unroll
        for (int i = 0; i < 4; i++) c += (dv[i] <= mid);
#pragma unroll
        for (int o = 16; o > 0; o >>= 1) c += __shfl_down_sync(0xffffffffu, c, o);
        if ((tid & 31) == 0) atomicAdd(&scount, c);
        __syncthreads();
        if (scount >= 21) hi = mid; else lo = mid + 1;
        __syncthreads();
    }
    if (tid == 0) {
        int n = 0;
        for (int k = 0; k < NLAT && n < 64; k++) {
            int kx = k & (RLAT - 1), ky = k >> 5;
            int dx = qx - kx, dy = qy - ky;
            if (dx * dx + dy * dy <= lo) kidx[q * 64 + (n++)] = k;
        }
        kcnt[q] = n;
    }
}

// ---------------------------------------------------------------------------
// Separable softmax factor
// ---------------------------------------------------------------------------
template <int RQ, int RK>
__global__ void k_factor(const float* __restrict__ rv, float* __restrict__ w) {
    int h = blockIdx.x;
    int tid = threadIdx.x;
    if (tid >= RQ) return;
    float s = head_scale(rv[h]);
    float qp = (float)tid * (1.0f / RQ);
    float mind = 1e30f;
    for (int k = 0; k < RK; k++) {
        float d = qp - (float)k * (1.0f / RK);
        d = 0.5f * d * d;
        mind = fminf(mind, d);
    }
    float sum = 0.f;
    for (int k = 0; k < RK; k++) {
        float d = qp - (float)k * (1.0f / RK);
        d = 0.5f * d * d;
        sum += expf(s * (mind - d));
    }
    float inv = 1.0f / sum;
    for (int k = 0; k < RK; k++) {
        float d = qp - (float)k * (1.0f / RK);
        d = 0.5f * d * d;
        w[(h * RQ + tid) * RK + k] = expf(s * (mind - d)) * inv;
    }
}

// ---------------------------------------------------------------------------
// Tensor-core GEMM (bf16x3 split): C = act(A @ W [+ A2 @ W2] + biases)
// BM=128, BN=128, K=128 per pass. 256 threads = 8 warps; warp w owns rows
// [w*16, w*16+16) x all 128 cols via m16n8k16 mma (16 n-tiles).
// Modes: AENC (A = gelu(x@enW+enb) on the fly), DUAL (second A/W pass),
// DOGELU (gelu output), DEC (rowwise dot with d2w + reduce -> scalar/row).
// ---------------------------------------------------------------------------
template <int AENC, int DUAL, int DOGELU, int DEC>
__global__ void __launch_bounds__(256, 1)
k_gemm(const float* __restrict__ A,
       const __nv_bfloat16* __restrict__ Bh, const __nv_bfloat16* __restrict__ Bl,
       const float* __restrict__ A2,
       const __nv_bfloat16* __restrict__ B2h, const __nv_bfloat16* __restrict__ B2l,
       const float* __restrict__ bias, const float* __restrict__ bias2,
       const float* __restrict__ x, const float* __restrict__ enw,
       const float* __restrict__ enb,
       const float* __restrict__ d2w, const float* __restrict__ d2b,
       float* __restrict__ C) {
    extern __shared__ __align__(16) char smem_raw[];
    __nv_bfloat16* sAh = (__nv_bfloat16*)smem_raw;         // [128][136]
    __nv_bfloat16* sAl = sAh + 128 * 136;
    __nv_bfloat16* sBh = sAl + 128 * 136;                  // [n:128][k:136]
    __nv_bfloat16* sBl = sBh + 128 * 136;

    int tid = threadIdx.x;
    int wid = tid >> 5, lane = tid & 31;
    int g = lane >> 2, s = lane & 3;
    size_t rbase = (size_t)blockIdx.x * 128;

    float acc[16][4];
#pragma unroll
    for (int j = 0; j < 16; j++)
#pragma unroll
        for (int e = 0; e < 4; e++) acc[j][e] = 0.f;

    const int NPASS = DUAL ? 2 : 1;
#pragma unroll
    for (int pass = 0; pass < NPASS; pass++) {
        const float* Ap = (DUAL && pass) ? A2 : A;
        const __nv_bfloat16* Bph = (DUAL && pass) ? B2h : Bh;
        const __nv_bfloat16* Bpl = (DUAL && pass) ? B2l : Bl;

        // ---- fill A tile (fp32 -> bf16 hi/lo) ----
        if (AENC && pass == 0) {
            int row = tid >> 1, half = tid & 1;
            size_t grow = rbase + row;
            float x0 = x[grow * 3 + 0], x1 = x[grow * 3 + 1], x2 = x[grow * 3 + 2];
#pragma unroll 8
            for (int c = 0; c < 64; c++) {
                int cc = half * 64 + c;
                float a = fmaf(x0, enw[cc],
                          fmaf(x1, enw[HID + cc],
                          fmaf(x2, enw[2 * HID + cc], enb[cc])));
                a = gelu_f(a);
                __nv_bfloat16 h, l;
                split_bf(a, h, l);
                sAh[row * 136 + cc] = h;
                sAl[row * 136 + cc] = l;
            }
        } else {
            const float4* A4 = (const float4*)(Ap + rbase * 128);
#pragma unroll
            for (int i = 0; i < 16; i++) {
                int idx = tid + i * 256;              // 4096 float4s
                int row = idx >> 5, c4 = (idx & 31) << 2;
                float4 v = A4[idx];
                __nv_bfloat16 h0, l0, h1, l1, h2, l2, h3, l3;
                split_bf(v.x, h0, l0); split_bf(v.y, h1, l1);
                split_bf(v.z, h2, l2); split_bf(v.w, h3, l3);
                __nv_bfloat162 hp0 = {h0, h1}, hp1 = {h2, h3};
                __nv_bfloat162 lp0 = {l0, l1}, lp1 = {l2, l3};
                *(__nv_bfloat162*)&sAh[row * 136 + c4 + 0] = hp0;
                *(__nv_bfloat162*)&sAh[row * 136 + c4 + 2] = hp1;
                *(__nv_bfloat162*)&sAl[row * 136 + c4 + 0] = lp0;
                *(__nv_bfloat162*)&sAl[row * 136 + c4 + 2] = lp1;
            }
        }
        // ---- fill B tile from pretransposed bf16 [n][k] ----
        {
            const uint4* Bh4 = (const uint4*)Bph;
            const uint4* Bl4 = (const uint4*)Bpl;
#pragma unroll
            for (int i = 0; i < 8; i++) {
                int idx8 = tid + i * 256;             // 2048 groups of 8 bf16
                int n = idx8 >> 4, k8 = (idx8 & 15) << 3;
                *(uint4*)&sBh[n * 136 + k8] = Bh4[idx8];
                *(uint4*)&sBl[n * 136 + k8] = Bl4[idx8];
            }
        }
        __syncthreads();

        // ---- main mma loop ----
        int arow = wid * 16 + g;
#pragma unroll
        for (int ks = 0; ks < 8; ks++) {
            int k0 = ks * 16;
            unsigned ah0 = *(const unsigned*)&sAh[(arow)     * 136 + k0 + 2 * s];
            unsigned ah1 = *(const unsigned*)&sAh[(arow + 8) * 136 + k0 + 2 * s];
            unsigned ah2 = *(const unsigned*)&sAh[(arow)     * 136 + k0 + 2 * s + 8];
            unsigned ah3 = *(const unsigned*)&sAh[(arow + 8) * 136 + k0 + 2 * s + 8];
            unsigned al0 = *(const unsigned*)&sAl[(arow)     * 136 + k0 + 2 * s];
            unsigned al1 = *(const unsigned*)&sAl[(arow + 8) * 136 + k0 + 2 * s];
            unsigned al2 = *(const unsigned*)&sAl[(arow)     * 136 + k0 + 2 * s + 8];
            unsigned al3 = *(const unsigned*)&sAl[(arow + 8) * 136 + k0 + 2 * s + 8];
#pragma unroll
            for (int j = 0; j < 16; j++) {
                int n = j * 8 + g;
                unsigned bh0 = *(const unsigned*)&sBh[n * 136 + k0 + 2 * s];
                unsigned bh1 = *(const unsigned*)&sBh[n * 136 + k0 + 2 * s + 8];
                unsigned bl0 = *(const unsigned*)&sBl[n * 136 + k0 + 2 * s];
                unsigned bl1 = *(const unsigned*)&sBl[n * 136 + k0 + 2 * s + 8];
                mma_bf16(acc[j], ah0, ah1, ah2, ah3, bh0, bh1);
                mma_bf16(acc[j], ah0, ah1, ah2, ah3, bl0, bl1);
                mma_bf16(acc[j], al0, al1, al2, al3, bh0, bh1);
            }
        }
        __syncthreads();
    }

    // ---- epilogue ----
    int r0 = wid * 16 + g;        // rows for c0,c1 ; r0+8 for c2,c3
    if (DEC) {
        float p0 = 0.f, p1 = 0.f;
#pragma unroll
        for (int j = 0; j < 16; j++) {
            int c = j * 8 + 2 * s;
            float b0 = bias ? bias[c] : 0.f;
            float b1 = bias ? bias[c + 1] : 0.f;
            float w0 = d2w[c], w1 = d2w[c + 1];
            float v0 = gelu_f(acc[j][0] + b0), v1 = gelu_f(acc[j][1] + b1);
            float v2 = gelu_f(acc[j][2] + b0), v3 = gelu_f(acc[j][3] + b1);
            p0 = fmaf(v0, w0, fmaf(v1, w1, p0));
            p1 = fmaf(v2, w0, fmaf(v3, w1, p1));
        }
        p0 += __shfl_xor_sync(0xffffffffu, p0, 1);
        p0 += __shfl_xor_sync(0xffffffffu, p0, 2);
        p1 += __shfl_xor_sync(0xffffffffu, p1, 1);
        p1 += __shfl_xor_sync(0xffffffffu, p1, 2);
        if (s == 0) {
            float db = d2b[0];
            C[rbase + r0] = p0 + db;
            C[rbase + r0 + 8] = p1 + db;
        }
    } else {
#pragma unroll
        for (int j = 0; j < 16; j++) {
            int c = j * 8 + 2 * s;
            float b0 = 0.f, b1 = 0.f;
            if (bias) {
                float2 bb = *(const float2*)&bias[c];
                b0 += bb.x; b1 += bb.y;
            }
            if (DUAL && bias2) {
                float2 bb = *(const float2*)&bias2[c];
                b0 += bb.x; b1 += bb.y;
            }
            float v0 = acc[j][0] + b0, v1 = acc[j][1] + b1;
            float v2 = acc[j][2] + b0, v3 = acc[j][3] + b1;
            if (DOGELU) {
                v0 = gelu_f(v0); v1 = gelu_f(v1);
                v2 = gelu_f(v2); v3 = gelu_f(v3);
            }
            float2 u0 = {v0, v1}, u1 = {v2, v3};
            *(float2*)&C[(rbase + r0) * 128 + c] = u0;
            *(float2*)&C[(rbase + r0 + 8) * 128 + c] = u1;
        }
    }
}

// ---------------------------------------------------------------------------
// Separable attention step 1 (contract ky)
// ---------------------------------------------------------------------------
template <int RQ, int RK>
__global__ void k_sepY(const float* __restrict__ V, const float* __restrict__ w,
                       float* __restrict__ T) {
    constexpr int QPT = RQ / 8;
    __shared__ float sW[RQ * RK];
    __shared__ float sV[RK * 128];
    int tid = threadIdx.x;
    int kxc = blockIdx.x;
    int b = blockIdx.y, h = blockIdx.z;
    const float* wh = w + h * RQ * RK;
    for (int i = tid; i < RQ * RK; i += 256) sW[i] = wh[i];
    for (int i = tid; i < RK * 128; i += 256) {
        int ky = i >> 7, col = i & 127;
        int kx = kxc * 8 + (col >> 4), vd = col & 15;
        sV[i] = V[(((size_t)b * RK + ky) * RK + kx) * 128 + h * 16 + vd];
    }
    __syncthreads();
    int qy0 = (tid >> 5) * QPT, col0 = (tid & 31) * 4;
    float acc[QPT][4];
#pragma unroll
    for (int i = 0; i < QPT; i++)
#pragma unroll
        for (int j = 0; j < 4; j++) acc[i][j] = 0.f;
#pragma unroll 4
    for (int ky = 0; ky < RK; ky++) {
        float4 v = *reinterpret_cast<const float4*>(&sV[ky * 128 + col0]);
#pragma unroll
        for (int i = 0; i < QPT; i++) {
            float a = sW[(qy0 + i) * RK + ky];
            acc[i][0] = fmaf(a, v.x, acc[i][0]);
            acc[i][1] = fmaf(a, v.y, acc[i][1]);
            acc[i][2] = fmaf(a, v.z, acc[i][2]);
            acc[i][3] = fmaf(a, v.w, acc[i][3]);
        }
    }
    int kx = kxc * 8 + (col0 >> 4), vd0 = col0 & 15;
#pragma unroll
    for (int i = 0; i < QPT; i++) {
        float4 r = make_float4(acc[i][0], acc[i][1], acc[i][2], acc[i][3]);
        *reinterpret_cast<float4*>(
            &T[(((size_t)b * RQ + qy0 + i) * RK + kx) * 128 + h * 16 + vd0]) = r;
    }
}

// ---------------------------------------------------------------------------
// Separable attention step 2 (contract kx), fused gelu
// ---------------------------------------------------------------------------
template <int RQ, int RK>
__global__ void k_sepX(const float* __restrict__ T, const float* __restrict__ w,
                       float* __restrict__ O) {
    constexpr int QPT2 = RQ * 16 / 256;
    __shared__ float sW[RQ * RK];
    __shared__ float sT[RK * 16];
    int tid = threadIdx.x;
    int qy = blockIdx.x;
    int b = blockIdx.y, h = blockIdx.z;
    const float* wh = w + h * RQ * RK;
    for (int i = tid; i < RQ * RK; i += 256) sW[i] = wh[i];
    for (int i = tid; i < RK * 16; i += 256) {
        int kx = i >> 4, vd = i & 15;
        sT[i] = T[(((size_t)b * RQ + qy) * RK + kx) * 128 + h * 16 + vd];
    }
    __syncthreads();
    int c = tid & 15;
    int qx0 = (tid >> 4) * QPT2;
    float acc[QPT2];
#pragma unroll
    for (int i = 0; i < QPT2; i++) acc[i] = 0.f;
#pragma unroll 4
    for (int kx = 0; kx < RK; kx++) {
        float v = sT[kx * 16 + c];
#pragma unroll
        for (int i = 0; i < QPT2; i++)
            acc[i] = fmaf(sW[(qx0 + i) * RK + kx], v, acc[i]);
    }
#pragma unroll
    for (int i = 0; i < QPT2; i++) {
        O[((size_t)b * RQ * RQ + qy * RQ + qx0 + i) * 128 + h * 16 + c] = gelu_f(acc[i]);
    }
}

// ---------------------------------------------------------------------------
// Sparse proc attention
// ---------------------------------------------------------------------------
__global__ void k_procatt(const float* __restrict__ V, const float* __restrict__ rv,
                          const int* __restrict__ kidx, const int* __restrict__ kcnt,
                          float* __restrict__ out) {
    int q = blockIdx.x;
    int bg = blockIdx.y;
    int tid = threadIdx.x;
    __shared__ int   sidx[64];
    __shared__ float sdist[64];
    __shared__ float sp[NH][64];
    __shared__ float sscale[NH];
    __shared__ float ssum[NH];
    int cnt = kcnt[q];
    if (tid < cnt) {
        int k = kidx[q * 64 + tid];
        sidx[tid] = k;
        int qx = q & 31, qy = q >> 5;
        int kx = k & 31, ky = k >> 5;
        float dx = (qx - kx) * (1.0f / RLAT), dy = (qy - ky) * (1.0f / RLAT);
        sdist[tid] = 0.5f * (dx * dx + dy * dy);
    }
    if (tid < NH) sscale[tid] = head_scale(rv[tid]);
    __syncthreads();
    for (int jj = tid; jj < NH * 64; jj += 256) {
        int h = jj >> 6, j = jj & 63;
        if (j < cnt) sp[h][j] = expf(-sscale[h] * sdist[j]);
    }
    __syncthreads();
    if (tid < NH) {
        float s = 0.f;
        for (int j = 0; j < cnt; j++) s += sp[tid][j];
        ssum[tid] = s;
    }
    __syncthreads();
    int b = bg * 2 + (tid >> 7);
    int c = tid & 127;
    int h = c >> 4;
    const float* Vb = V + (size_t)b * NLAT * 128 + c;
    float acc = 0.f;
    int j = 0;
    for (; j + 4 <= cnt; j += 4) {
        float p0 = sp[h][j], p1 = sp[h][j + 1], p2 = sp[h][j + 2], p3 = sp[h][j + 3];
        int i0 = sidx[j], i1 = sidx[j + 1], i2 = sidx[j + 2], i3 = sidx[j + 3];
        float v0 = Vb[(size_t)i0 * 128];
        float v1 = Vb[(size_t)i1 * 128];
        float v2 = Vb[(size_t)i2 * 128];
        float v3 = Vb[(size_t)i3 * 128];
        acc = fmaf(p0, v0, acc);
        acc = fmaf(p1, v1, acc);
        acc = fmaf(p2, v2, acc);
        acc = fmaf(p3, v3, acc);
    }
    for (; j < cnt; j++) acc = fmaf(sp[h][j], Vb[(size_t)sidx[j] * 128], acc);
    out[((size_t)b * NLAT + q) * 128 + c] = gelu_f(acc / ssum[h]);
}

// ---------------------------------------------------------------------------
// Launcher
// ---------------------------------------------------------------------------
extern "C" void kernel_launch(void* const* d_in, const int* in_sizes, int n_in,
                              void* d_out, int out_size) {
    const float* x        = (const float*)d_in[0];
    const float* en_w     = (const float*)d_in[1];
    const float* en_b     = (const float*)d_in[2];
    const float* down_r   = (const float*)d_in[3];
    const float* down_w   = (const float*)d_in[4];
    const float* pa_r     = (const float*)d_in[5];
    const float* pa_w     = (const float*)d_in[6];
    const float* mlp1_w   = (const float*)d_in[7];
    const float* mlp1_b   = (const float*)d_in[8];
    const float* mlp2_w   = (const float*)d_in[9];
    const float* mlp2_b   = (const float*)d_in[10];
    const float* res_w    = (const float*)d_in[11];
    const float* res_b    = (const float*)d_in[12];
    const float* up_r     = (const float*)d_in[13];
    const float* up_w     = (const float*)d_in[14];
    const float* de1_w    = (const float*)d_in[15];
    const float* de1_b    = (const float*)d_in[16];
    const float* de2_w    = (const float*)d_in[17];
    const float* de2_b    = (const float*)d_in[18];
    float* out = (float*)d_out;

    float *h0, *val, *hup, *hA, *hB, *pa, *t1, *wdn, *wup;
    int *kidx, *kcnt;
    __nv_bfloat16 *bwh, *bwl;
    cudaGetSymbolAddress((void**)&h0,   g_h0);
    cudaGetSymbolAddress((void**)&val,  g_val);
    cudaGetSymbolAddress((void**)&hup,  g_hup);
    cudaGetSymbolAddress((void**)&hA,   g_hA);
    cudaGetSymbolAddress((void**)&hB,   g_hB);
    cudaGetSymbolAddress((void**)&pa,   g_pa);
    cudaGetSymbolAddress((void**)&t1,   g_t1);
    cudaGetSymbolAddress((void**)&wdn,  g_wdn);
    cudaGetSymbolAddress((void**)&wup,  g_wup);
    cudaGetSymbolAddress((void**)&kidx, g_kidx);
    cudaGetSymbolAddress((void**)&kcnt, g_kcnt);
    cudaGetSymbolAddress((void**)&bwh,  g_bwh);
    cudaGetSymbolAddress((void**)&bwl,  g_bwl);

    // opt-in smem (idempotent; first call happens outside graph capture)
    cudaFuncSetAttribute(k_gemm<1,0,0,0>, cudaFuncAttributeMaxDynamicSharedMemorySize, GEMM_SMEM);
    cudaFuncSetAttribute(k_gemm<0,0,0,0>, cudaFuncAttributeMaxDynamicSharedMemorySize, GEMM_SMEM);
    cudaFuncSetAttribute(k_gemm<0,0,1,0>, cudaFuncAttributeMaxDynamicSharedMemorySize, GEMM_SMEM);
    cudaFuncSetAttribute(k_gemm<0,1,1,0>, cudaFuncAttributeMaxDynamicSharedMemorySize, GEMM_SMEM);
    cudaFuncSetAttribute(k_gemm<0,0,1,1>, cudaFuncAttributeMaxDynamicSharedMemorySize, GEMM_SMEM);

    const int M_IN  = BATCH * NIN;   // 65536
    const int M_LAT = BATCH * NLAT;  // 16384
    const size_t MS = (size_t)HID * HID;

    // ---- weight prep: idx 0 down_w, 1-3 pa_w, 4 up_w, 5-7 mlp1, 8-10 mlp2,
    //      11-13 res, 14 de1  (bre on 0-4) ----
    BWList L;
    L.w[0] = down_w;
    L.w[1] = pa_w;          L.w[2] = pa_w + 16384;  L.w[3] = pa_w + 32768;
    L.w[4] = up_w;
    L.w[5] = mlp1_w;        L.w[6] = mlp1_w + MS;   L.w[7] = mlp1_w + 2 * MS;
    L.w[8] = mlp2_w;        L.w[9] = mlp2_w + MS;   L.w[10] = mlp2_w + 2 * MS;
    L.w[11] = res_w;        L.w[12] = res_w + MS;   L.w[13] = res_w + 2 * MS;
    L.w[14] = de1_w;
    L.bre_mask = 0x1F;
    {
        dim3 g(64, NWMAT);
        k_prepB<<<g, 256>>>(L, bwh, bwl);
    }
    k_knn<<<NLAT, 256>>>(kidx, kcnt);
    k_factor<RLAT, RIN><<<NH, 64>>>(down_r, wdn);
    k_factor<RIN, RLAT><<<NH, 64>>>(up_r, wup);

#define BW(i) (bwh + (size_t)(i) * MS), (bwl + (size_t)(i) * MS)

    // ---- down: fused encoder + value GEMM, then separable attention ----
    k_gemm<1,0,0,0><<<M_IN / 128, 256, GEMM_SMEM>>>(
        nullptr, BW(0), nullptr, nullptr, nullptr,
        nullptr, nullptr, x, en_w, en_b, nullptr, nullptr, val);
    {
        dim3 g1(RIN / 8, BATCH, NH);
        k_sepY<RLAT, RIN><<<g1, 256>>>(val, wdn, h0);
        dim3 g2(RLAT, BATCH, NH);
        k_sepX<RLAT, RIN><<<g2, 256>>>(h0, wdn, hA);
    }

    // ---- processor blocks ----
    float* hin = hA;
    float* hout = hB;
    for (int i = 0; i < 3; i++) {
        k_gemm<0,0,0,0><<<M_LAT / 128, 256, GEMM_SMEM>>>(
            hin, BW(1 + i), nullptr, nullptr, nullptr,
            nullptr, nullptr, nullptr, nullptr, nullptr, nullptr, nullptr, val);
        {
            dim3 g(NLAT, 8);
            k_procatt<<<g, 256>>>(val, pa_r + i * NH, kidx, kcnt, pa);
        }
        k_gemm<0,0,1,0><<<M_LAT / 128, 256, GEMM_SMEM>>>(
            pa, BW(5 + i), nullptr, nullptr, nullptr,
            mlp1_b + i * HID, nullptr, nullptr, nullptr, nullptr, nullptr, nullptr, t1);
        k_gemm<0,1,1,0><<<M_LAT / 128, 256, GEMM_SMEM>>>(
            t1, BW(8 + i), hin, BW(11 + i),
            mlp2_b + i * HID, res_b + i * HID,
            nullptr, nullptr, nullptr, nullptr, nullptr, hout);
        float* tmp = hin; hin = hout; hout = tmp;
    }

    // ---- up: value GEMM + separable attention ----
    k_gemm<0,0,0,0><<<M_LAT / 128, 256, GEMM_SMEM>>>(
        hin, BW(4), nullptr, nullptr, nullptr,
        nullptr, nullptr, nullptr, nullptr, nullptr, nullptr, nullptr, val);
    {
        dim3 g1(RLAT / 8, BATCH, NH);
        k_sepY<RIN, RLAT><<<g1, 256>>>(val, wup, h0);
        dim3 g2(RIN, BATCH, NH);
        k_sepX<RIN, RLAT><<<g2, 256>>>(h0, wup, hup);
    }

    // ---- fused decoder ----
    k_gemm<0,0,1,1><<<M_IN / 128, 256, GEMM_SMEM>>>(
        hup, BW(14), nullptr, nullptr, nullptr,
        de1_b, nullptr, nullptr, nullptr, nullptr, de2_w, de2_b, out);
#undef BW
}

// round 6
// speedup vs baseline: 4.7640x; 1.1171x over previous
#include <cuda_runtime.h>
#include <cuda_bf16.h>
#include <math.h>

// ---------------------------------------------------------------------------
// Problem constants
// ---------------------------------------------------------------------------
#define BATCH   16
#define NH      8
#define HID     128
#define VD      16
#define RIN     64
#define RLAT    32
#define NIN     (RIN*RIN)   // 4096
#define NLAT    (RLAT*RLAT) // 1024
#define PI_F    3.14159265358979323846f

#define NWMAT   15
#define GEMM_SMEM (4*128*136*2)   // sAh,sAl,sBh,sBl : 139264 bytes

// procatt tiled smem budget
#define KMAX  40
#define PROC_SMEM (256*128*4 + 64*KMAX*8*4 + 64*KMAX*4 + 64*4 + 64*8*4)  // 225536

// ---------------------------------------------------------------------------
// Scratch buffers
// ---------------------------------------------------------------------------
__device__ float g_h0 [BATCH*NIN*HID];
__device__ float g_val[BATCH*NIN*HID];
__device__ float g_hup[BATCH*NIN*HID];
__device__ float g_hA [BATCH*NLAT*HID];
__device__ float g_hB [BATCH*NLAT*HID];
__device__ float g_pa [BATCH*NLAT*HID];
__device__ float g_t1 [BATCH*NLAT*HID];
__device__ float g_wdn[NH*RLAT*RIN];
__device__ float g_wup[NH*RIN*RLAT];
__device__ int   g_kidx[NLAT*64];
__device__ int   g_kcnt[NLAT];
__device__ __align__(16) __nv_bfloat16 g_bwh[NWMAT*HID*HID];
__device__ __align__(16) __nv_bfloat16 g_bwl[NWMAT*HID*HID];

// ---------------------------------------------------------------------------
// Helpers
// ---------------------------------------------------------------------------
__device__ __forceinline__ float gelu_f(float x) {
    const float c = 0.7978845608028654f;
    float y = c * fmaf(0.044715f * x, x * x, x);
    return x / (1.0f + __expf(-2.0f * y));
}

__device__ __forceinline__ float head_scale(float r) {
    return tanf(0.25f * PI_F * (1.0f - 1e-7f) * (1.0f + sinf(r)));
}

__device__ __forceinline__ void split_bf(float v, __nv_bfloat16& h, __nv_bfloat16& l) {
    h = __float2bfloat16(v);
    l = __float2bfloat16(v - __bfloat162float(h));
}

__device__ __forceinline__ void mma_bf16(float* d,
        unsigned a0, unsigned a1, unsigned a2, unsigned a3,
        unsigned b0, unsigned b1) {
    asm volatile(
        "mma.sync.aligned.m16n8k16.row.col.f32.bf16.bf16.f32 "
        "{%0,%1,%2,%3}, {%4,%5,%6,%7}, {%8,%9}, {%0,%1,%2,%3};"
        : "+f"(d[0]), "+f"(d[1]), "+f"(d[2]), "+f"(d[3])
        : "r"(a0), "r"(a1), "r"(a2), "r"(a3), "r"(b0), "r"(b1));
}

__device__ __forceinline__ void ldsm4(unsigned& r0, unsigned& r1, unsigned& r2,
                                      unsigned& r3, unsigned addr) {
    asm volatile("ldmatrix.sync.aligned.m8n8.x4.shared.b16 {%0,%1,%2,%3}, [%4];"
        : "=r"(r0), "=r"(r1), "=r"(r2), "=r"(r3) : "r"(addr));
}

// ---------------------------------------------------------------------------
// Weight prep (bf16 hi/lo, transposed to [n][k])
// ---------------------------------------------------------------------------
struct BWList { const float* w[NWMAT]; unsigned bre_mask; };

__global__ void k_prepB(BWList L, __nv_bfloat16* __restrict__ outh,
                        __nv_bfloat16* __restrict__ outl) {
    int mat = blockIdx.y;
    const float* w = L.w[mat];
    int bre = (L.bre_mask >> mat) & 1;
    int idx = blockIdx.x * 256 + threadIdx.x;
    int k = idx >> 7, n = idx & 127;
    float v;
    if (bre) {
        int h = n >> 4, vd = n & 15;
        v = w[((size_t)h * HID + k) * VD + vd];
    } else {
        v = w[k * HID + n];
    }
    __nv_bfloat16 hi, lo;
    split_bf(v, hi, lo);
    size_t o = (size_t)mat * HID * HID + n * HID + k;
    outh[o] = hi;
    outl[o] = lo;
}

// ---------------------------------------------------------------------------
// kNN precompute: binary search threshold + parallel prefix-scan collection
// ---------------------------------------------------------------------------
__global__ void k_knn(int* __restrict__ kidx, int* __restrict__ kcnt) {
    int q = blockIdx.x;
    int tid = threadIdx.x, lane = tid & 31, w = tid >> 5;
    int qx = q & (RLAT - 1), qy = q >> 5;
    int dv[4];
#pragma unroll
    for (int i = 0; i < 4; i++) {
        int k = tid * 4 + i;
        int kx = k & (RLAT - 1), ky = k >> 5;
        int dx = qx - kx, dy = qy - ky;
        dv[i] = dx * dx + dy * dy;
    }
    __shared__ int scount;
    int lo = 0, hi = 2 * 31 * 31;
    while (lo < hi) {
        int mid = (lo + hi) >> 1;
        if (tid == 0) scount = 0;
        __syncthreads();
        int c = 0;
#pragma unroll
        for (int i = 0; i < 4; i++) c += (dv[i] <= mid);
#pragma unroll
        for (int o = 16; o > 0; o >>= 1) c += __shfl_down_sync(0xffffffffu, c, o);
        if (lane == 0) atomicAdd(&scount, c);
        __syncthreads();
        if (scount >= 21) hi = mid; else lo = mid + 1;
        __syncthreads();
    }
    // deterministic parallel collection (ascending key = (tid, i) lexicographic)
    int sel[4], cnt_t = 0;
#pragma unroll
    for (int i = 0; i < 4; i++) { sel[i] = (dv[i] <= lo); cnt_t += sel[i]; }
    int incl = cnt_t;
#pragma unroll
    for (int o = 1; o < 32; o <<= 1) {
        int v = __shfl_up_sync(0xffffffffu, incl, o);
        if (lane >= o) incl += v;
    }
    __shared__ int wsum[8], wbase[8];
    if (lane == 31) wsum[w] = incl;
    __syncthreads();
    if (tid == 0) {
        int b = 0;
        for (int i = 0; i < 8; i++) { wbase[i] = b; b += wsum[i]; }
        kcnt[q] = b;
    }
    __syncthreads();
    int pos = wbase[w] + incl - cnt_t;
#pragma unroll
    for (int i = 0; i < 4; i++) {
        if (sel[i] && pos < 64) kidx[q * 64 + pos] = tid * 4 + i;
        pos += sel[i];
    }
}

// ---------------------------------------------------------------------------
// Separable softmax factor: warp per query, lanes over k
// ---------------------------------------------------------------------------
template <int RQ, int RK>
__global__ void k_factor(const float* __restrict__ rv, float* __restrict__ w) {
    constexpr int KP = RK / 32;
    int h = blockIdx.x;
    int tid = threadIdx.x, lane = tid & 31, wp = tid >> 5;
    float s = head_scale(rv[h]);
    for (int q = wp; q < RQ; q += 8) {
        float qp = (float)q * (1.0f / RQ);
        float d[KP];
        float mind = 1e30f;
#pragma unroll
        for (int i = 0; i < KP; i++) {
            int k = lane + i * 32;
            float dd = qp - (float)k * (1.0f / RK);
            d[i] = 0.5f * dd * dd;
            mind = fminf(mind, d[i]);
        }
#pragma unroll
        for (int o = 16; o > 0; o >>= 1)
            mind = fminf(mind, __shfl_xor_sync(0xffffffffu, mind, o));
        float p[KP], sum = 0.f;
#pragma unroll
        for (int i = 0; i < KP; i++) { p[i] = __expf(s * (mind - d[i])); sum += p[i]; }
#pragma unroll
        for (int o = 16; o > 0; o >>= 1)
            sum += __shfl_xor_sync(0xffffffffu, sum, o);
        float inv = 1.0f / sum;
#pragma unroll
        for (int i = 0; i < KP; i++)
            w[(h * RQ + q) * RK + lane + i * 32] = p[i] * inv;
    }
}

// ---------------------------------------------------------------------------
// Tensor-core GEMM (bf16x3 split) with ldmatrix fragment loads
// ---------------------------------------------------------------------------
template <int AENC, int DUAL, int DOGELU, int DEC>
__global__ void __launch_bounds__(256, 1)
k_gemm(const float* __restrict__ A,
       const __nv_bfloat16* __restrict__ Bh, const __nv_bfloat16* __restrict__ Bl,
       const float* __restrict__ A2,
       const __nv_bfloat16* __restrict__ B2h, const __nv_bfloat16* __restrict__ B2l,
       const float* __restrict__ bias, const float* __restrict__ bias2,
       const float* __restrict__ x, const float* __restrict__ enw,
       const float* __restrict__ enb,
       const float* __restrict__ d2w, const float* __restrict__ d2b,
       float* __restrict__ C) {
    extern __shared__ __align__(16) char smem_raw[];
    __nv_bfloat16* sAh = (__nv_bfloat16*)smem_raw;
    __nv_bfloat16* sAl = sAh + 128 * 136;
    __nv_bfloat16* sBh = sAl + 128 * 136;
    __nv_bfloat16* sBl = sBh + 128 * 136;

    int tid = threadIdx.x;
    int wid = tid >> 5, lane = tid & 31;
    int g = lane >> 2, s = lane & 3;
    size_t rbase = (size_t)blockIdx.x * 128;

    // ldmatrix addresses
    unsigned sAh_b = (unsigned)__cvta_generic_to_shared(sAh);
    unsigned sAl_b = (unsigned)__cvta_generic_to_shared(sAl);
    unsigned sBh_b = (unsigned)__cvta_generic_to_shared(sBh);
    unsigned sBl_b = (unsigned)__cvta_generic_to_shared(sBl);
    int arowf = wid * 16 + (lane & 15);
    unsigned aoff = (unsigned)((arowf * 136 + ((lane >> 4) << 3)) * 2);
    int brow = (lane & 7) + ((lane >> 4) << 3);
    unsigned boff = (unsigned)((brow * 136 + (((lane >> 3) & 1) << 3)) * 2);

    float acc[16][4];
#pragma unroll
    for (int j = 0; j < 16; j++)
#pragma unroll
        for (int e = 0; e < 4; e++) acc[j][e] = 0.f;

    const int NPASS = DUAL ? 2 : 1;
#pragma unroll
    for (int pass = 0; pass < NPASS; pass++) {
        const float* Ap = (DUAL && pass) ? A2 : A;
        const __nv_bfloat16* Bph = (DUAL && pass) ? B2h : Bh;
        const __nv_bfloat16* Bpl = (DUAL && pass) ? B2l : Bl;

        if (AENC && pass == 0) {
            int row = tid >> 1, half = tid & 1;
            size_t grow = rbase + row;
            float x0 = x[grow * 3 + 0], x1 = x[grow * 3 + 1], x2 = x[grow * 3 + 2];
#pragma unroll 8
            for (int c = 0; c < 64; c++) {
                int cc = half * 64 + c;
                float a = fmaf(x0, enw[cc],
                          fmaf(x1, enw[HID + cc],
                          fmaf(x2, enw[2 * HID + cc], enb[cc])));
                a = gelu_f(a);
                __nv_bfloat16 h, l;
                split_bf(a, h, l);
                sAh[row * 136 + cc] = h;
                sAl[row * 136 + cc] = l;
            }
        } else {
            const float4* A4 = (const float4*)(Ap + rbase * 128);
#pragma unroll
            for (int i = 0; i < 16; i++) {
                int idx = tid + i * 256;
                int row = idx >> 5, c4 = (idx & 31) << 2;
                float4 v = A4[idx];
                __nv_bfloat16 h0, l0, h1, l1, h2, l2, h3, l3;
                split_bf(v.x, h0, l0); split_bf(v.y, h1, l1);
                split_bf(v.z, h2, l2); split_bf(v.w, h3, l3);
                __nv_bfloat162 hp0 = {h0, h1}, hp1 = {h2, h3};
                __nv_bfloat162 lp0 = {l0, l1}, lp1 = {l2, l3};
                *(__nv_bfloat162*)&sAh[row * 136 + c4 + 0] = hp0;
                *(__nv_bfloat162*)&sAh[row * 136 + c4 + 2] = hp1;
                *(__nv_bfloat162*)&sAl[row * 136 + c4 + 0] = lp0;
                *(__nv_bfloat162*)&sAl[row * 136 + c4 + 2] = lp1;
            }
        }
        {
            const uint4* Bh4 = (const uint4*)Bph;
            const uint4* Bl4 = (const uint4*)Bpl;
#pragma unroll
            for (int i = 0; i < 8; i++) {
                int idx8 = tid + i * 256;
                int n = idx8 >> 4, k8 = (idx8 & 15) << 3;
                *(uint4*)&sBh[n * 136 + k8] = Bh4[idx8];
                *(uint4*)&sBl[n * 136 + k8] = Bl4[idx8];
            }
        }
        __syncthreads();

#pragma unroll
        for (int ks = 0; ks < 8; ks++) {
            unsigned kb = (unsigned)(ks * 16 * 2);
            unsigned ah0, ah1, ah2, ah3, al0, al1, al2, al3;
            ldsm4(ah0, ah1, ah2, ah3, sAh_b + aoff + kb);
            ldsm4(al0, al1, al2, al3, sAl_b + aoff + kb);
#pragma unroll
            for (int j2 = 0; j2 < 8; j2++) {
                unsigned bofs = boff + (unsigned)(j2 * 16 * 136 * 2) + kb;
                unsigned bh0, bh1, bh2, bh3, bl0, bl1, bl2, bl3;
                ldsm4(bh0, bh1, bh2, bh3, sBh_b + bofs);
                ldsm4(bl0, bl1, bl2, bl3, sBl_b + bofs);
                mma_bf16(acc[2 * j2],     ah0, ah1, ah2, ah3, bh0, bh1);
                mma_bf16(acc[2 * j2],     ah0, ah1, ah2, ah3, bl0, bl1);
                mma_bf16(acc[2 * j2],     al0, al1, al2, al3, bh0, bh1);
                mma_bf16(acc[2 * j2 + 1], ah0, ah1, ah2, ah3, bh2, bh3);
                mma_bf16(acc[2 * j2 + 1], ah0, ah1, ah2, ah3, bl2, bl3);
                mma_bf16(acc[2 * j2 + 1], al0, al1, al2, al3, bh2, bh3);
            }
        }
        __syncthreads();
    }

    int r0 = wid * 16 + g;
    if (DEC) {
        float p0 = 0.f, p1 = 0.f;
#pragma unroll
        for (int j = 0; j < 16; j++) {
            int c = j * 8 + 2 * s;
            float b0 = bias ? bias[c] : 0.f;
            float b1 = bias ? bias[c + 1] : 0.f;
            float w0 = d2w[c], w1 = d2w[c + 1];
            float v0 = gelu_f(acc[j][0] + b0), v1 = gelu_f(acc[j][1] + b1);
            float v2 = gelu_f(acc[j][2] + b0), v3 = gelu_f(acc[j][3] + b1);
            p0 = fmaf(v0, w0, fmaf(v1, w1, p0));
            p1 = fmaf(v2, w0, fmaf(v3, w1, p1));
        }
        p0 += __shfl_xor_sync(0xffffffffu, p0, 1);
        p0 += __shfl_xor_sync(0xffffffffu, p0, 2);
        p1 += __shfl_xor_sync(0xffffffffu, p1, 1);
        p1 += __shfl_xor_sync(0xffffffffu, p1, 2);
        if (s == 0) {
            float db = d2b[0];
            C[rbase + r0] = p0 + db;
            C[rbase + r0 + 8] = p1 + db;
        }
    } else {
#pragma unroll
        for (int j = 0; j < 16; j++) {
            int c = j * 8 + 2 * s;
            float b0 = 0.f, b1 = 0.f;
            if (bias) {
                float2 bb = *(const float2*)&bias[c];
                b0 += bb.x; b1 += bb.y;
            }
            if (DUAL && bias2) {
                float2 bb = *(const float2*)&bias2[c];
                b0 += bb.x; b1 += bb.y;
            }
            float v0 = acc[j][0] + b0, v1 = acc[j][1] + b1;
            float v2 = acc[j][2] + b0, v3 = acc[j][3] + b1;
            if (DOGELU) {
                v0 = gelu_f(v0); v1 = gelu_f(v1);
                v2 = gelu_f(v2); v3 = gelu_f(v3);
            }
            float2 u0 = {v0, v1}, u1 = {v2, v3};
            *(float2*)&C[(rbase + r0) * 128 + c] = u0;
            *(float2*)&C[(rbase + r0 + 8) * 128 + c] = u1;
        }
    }
}

// ---------------------------------------------------------------------------
// Separable attention step 1 (contract ky)
// ---------------------------------------------------------------------------
template <int RQ, int RK>
__global__ void k_sepY(const float* __restrict__ V, const float* __restrict__ w,
                       float* __restrict__ T) {
    constexpr int QPT = RQ / 8;
    __shared__ float sW[RQ * RK];
    __shared__ float sV[RK * 128];
    int tid = threadIdx.x;
    int kxc = blockIdx.x;
    int b = blockIdx.y, h = blockIdx.z;
    const float* wh = w + h * RQ * RK;
    for (int i = tid; i < RQ * RK; i += 256) sW[i] = wh[i];
    for (int i = tid; i < RK * 128; i += 256) {
        int ky = i >> 7, col = i & 127;
        int kx = kxc * 8 + (col >> 4), vd = col & 15;
        sV[i] = V[(((size_t)b * RK + ky) * RK + kx) * 128 + h * 16 + vd];
    }
    __syncthreads();
    int qy0 = (tid >> 5) * QPT, col0 = (tid & 31) * 4;
    float acc[QPT][4];
#pragma unroll
    for (int i = 0; i < QPT; i++)
#pragma unroll
        for (int j = 0; j < 4; j++) acc[i][j] = 0.f;
#pragma unroll 4
    for (int ky = 0; ky < RK; ky++) {
        float4 v = *reinterpret_cast<const float4*>(&sV[ky * 128 + col0]);
#pragma unroll
        for (int i = 0; i < QPT; i++) {
            float a = sW[(qy0 + i) * RK + ky];
            acc[i][0] = fmaf(a, v.x, acc[i][0]);
            acc[i][1] = fmaf(a, v.y, acc[i][1]);
            acc[i][2] = fmaf(a, v.z, acc[i][2]);
            acc[i][3] = fmaf(a, v.w, acc[i][3]);
        }
    }
    int kx = kxc * 8 + (col0 >> 4), vd0 = col0 & 15;
#pragma unroll
    for (int i = 0; i < QPT; i++) {
        float4 r = make_float4(acc[i][0], acc[i][1], acc[i][2], acc[i][3]);
        *reinterpret_cast<float4*>(
            &T[(((size_t)b * RQ + qy0 + i) * RK + kx) * 128 + h * 16 + vd0]) = r;
    }
}

// ---------------------------------------------------------------------------
// Separable attention step 2 (contract kx), fused gelu
// ---------------------------------------------------------------------------
template <int RQ, int RK>
__global__ void k_sepX(const float* __restrict__ T, const float* __restrict__ w,
                       float* __restrict__ O) {
    constexpr int QPT2 = RQ * 16 / 256;
    __shared__ float sW[RQ * RK];
    __shared__ float sT[RK * 16];
    int tid = threadIdx.x;
    int qy = blockIdx.x;
    int b = blockIdx.y, h = blockIdx.z;
    const float* wh = w + h * RQ * RK;
    for (int i = tid; i < RQ * RK; i += 256) sW[i] = wh[i];
    for (int i = tid; i < RK * 16; i += 256) {
        int kx = i >> 4, vd = i & 15;
        sT[i] = T[(((size_t)b * RQ + qy) * RK + kx) * 128 + h * 16 + vd];
    }
    __syncthreads();
    int c = tid & 15;
    int qx0 = (tid >> 4) * QPT2;
    float acc[QPT2];
#pragma unroll
    for (int i = 0; i < QPT2; i++) acc[i] = 0.f;
#pragma unroll 4
    for (int kx = 0; kx < RK; kx++) {
        float v = sT[kx * 16 + c];
#pragma unroll
        for (int i = 0; i < QPT2; i++)
            acc[i] = fmaf(sW[(qx0 + i) * RK + kx], v, acc[i]);
    }
#pragma unroll
    for (int i = 0; i < QPT2; i++) {
        O[((size_t)b * RQ * RQ + qy * RQ + qx0 + i) * 128 + h * 16 + c] = gelu_f(acc[i]);
    }
}

// ---------------------------------------------------------------------------
// Tiled sparse proc attention: block = 8x8 query tile x 1 batch.
// V row union (16x16 with halo 4) staged in smem; probs in smem [q][j][h].
// ---------------------------------------------------------------------------
__global__ void __launch_bounds__(256, 1)
k_procatt(const float* __restrict__ V, const float* __restrict__ rv,
          const int* __restrict__ kidx, const int* __restrict__ kcnt,
          float* __restrict__ out) {
    extern __shared__ float psm[];
    float* sV   = psm;                        // 256*128
    float* sp   = sV + 256 * 128;             // 64*KMAX*8
    int*   skl  = (int*)(sp + 64 * KMAX * 8); // 64*KMAX
    int*   scnt = skl + 64 * KMAX;            // 64
    float* sinv = (float*)(scnt + 64);        // 64*8
    __shared__ float sscale[NH];

    int tile = blockIdx.x;      // 16 tiles of 8x8
    int b = blockIdx.y;
    int tx = tile & 3, ty = tile >> 2;
    int x0 = tx * 8 - 4, y0 = ty * 8 - 4;
    int tid = threadIdx.x, lane = tid & 31, w = tid >> 5;

    if (tid < NH) sscale[tid] = head_scale(rv[tid]);

    // stage V rows (union with halo)
    const float4* V4 = (const float4*)V;
    for (int r = w; r < 256; r += 8) {
        int ix = r & 15, iy = r >> 4;
        int kx = x0 + ix, ky = y0 + iy;
        if ((unsigned)kx < 32u && (unsigned)ky < 32u) {
            int k = ky * 32 + kx;
            *(float4*)&sV[r * 128 + lane * 4] = V4[((size_t)b * NLAT + k) * 32 + lane];
        }
    }
    // counts + local neighbor indices
    if (tid < 64) {
        int qx = tx * 8 + (tid & 7), qy = ty * 8 + (tid >> 3);
        scnt[tid] = kcnt[qy * 32 + qx];
    }
    for (int i = tid; i < 64 * KMAX; i += 256) {
        int ql = i / KMAX, j = i - ql * KMAX;
        if (j < 64) {
            int qx = tx * 8 + (ql & 7), qy = ty * 8 + (ql >> 3);
            int gk = kidx[(qy * 32 + qx) * 64 + j];
            int kx = gk & 31, ky = gk >> 5;
            skl[i] = (ky - y0) * 16 + (kx - x0);
        }
    }
    __syncthreads();
    // probabilities sp[q][j][h]
    for (int i = tid; i < 64 * KMAX; i += 256) {
        int ql = i / KMAX, j = i - ql * KMAX;
        if (j < scnt[ql]) {
            int kl = skl[i];
            int ix = kl & 15, iy = kl >> 4;
            float dx = (float)(ix - 4 - (ql & 7)) * (1.0f / RLAT);
            float dy = (float)(iy - 4 - (ql >> 3)) * (1.0f / RLAT);
            float dist = 0.5f * (dx * dx + dy * dy);
#pragma unroll
            for (int h = 0; h < NH; h++)
                sp[i * 8 + h] = __expf(-sscale[h] * dist);
        }
    }
    __syncthreads();
    // per (q,h) inverse sums
    for (int hq = tid; hq < 512; hq += 256) {
        int ql = hq >> 3, h = hq & 7;
        int cnt = scnt[ql];
        float sum = 0.f;
        for (int j = 0; j < cnt; j++) sum += sp[(ql * KMAX + j) * 8 + h];
        sinv[ql * 8 + h] = 1.0f / sum;
    }
    __syncthreads();

    // main: warp = qy row of tile, lane = 4-channel group
    int qy_l = w;            // 0..7
    int cg = lane;           // 0..31 -> channels cg*4..cg*4+3
    int h = cg >> 2;
    const float4* sV4 = (const float4*)sV;
#pragma unroll
    for (int qx_l = 0; qx_l < 8; qx_l++) {
        int ql = qy_l * 8 + qx_l;
        int cnt = scnt[ql];
        int base = ql * KMAX;
        float4 acc = make_float4(0.f, 0.f, 0.f, 0.f);
        for (int j = 0; j < cnt; j++) {
            float p = sp[(base + j) * 8 + h];
            float4 v = sV4[skl[base + j] * 32 + cg];
            acc.x = fmaf(p, v.x, acc.x);
            acc.y = fmaf(p, v.y, acc.y);
            acc.z = fmaf(p, v.z, acc.z);
            acc.w = fmaf(p, v.w, acc.w);
        }
        float inv = sinv[ql * 8 + h];
        float4 r;
        r.x = gelu_f(acc.x * inv);
        r.y = gelu_f(acc.y * inv);
        r.z = gelu_f(acc.z * inv);
        r.w = gelu_f(acc.w * inv);
        int qglob = (ty * 8 + qy_l) * 32 + tx * 8 + qx_l;
        *(float4*)&out[((size_t)b * NLAT + qglob) * 128 + cg * 4] = r;
    }
}

// ---------------------------------------------------------------------------
// Launcher
// ---------------------------------------------------------------------------
extern "C" void kernel_launch(void* const* d_in, const int* in_sizes, int n_in,
                              void* d_out, int out_size) {
    const float* x        = (const float*)d_in[0];
    const float* en_w     = (const float*)d_in[1];
    const float* en_b     = (const float*)d_in[2];
    const float* down_r   = (const float*)d_in[3];
    const float* down_w   = (const float*)d_in[4];
    const float* pa_r     = (const float*)d_in[5];
    const float* pa_w     = (const float*)d_in[6];
    const float* mlp1_w   = (const float*)d_in[7];
    const float* mlp1_b   = (const float*)d_in[8];
    const float* mlp2_w   = (const float*)d_in[9];
    const float* mlp2_b   = (const float*)d_in[10];
    const float* res_w    = (const float*)d_in[11];
    const float* res_b    = (const float*)d_in[12];
    const float* up_r     = (const float*)d_in[13];
    const float* up_w     = (const float*)d_in[14];
    const float* de1_w    = (const float*)d_in[15];
    const float* de1_b    = (const float*)d_in[16];
    const float* de2_w    = (const float*)d_in[17];
    const float* de2_b    = (const float*)d_in[18];
    float* out = (float*)d_out;

    float *h0, *val, *hup, *hA, *hB, *pa, *t1, *wdn, *wup;
    int *kidx, *kcnt;
    __nv_bfloat16 *bwh, *bwl;
    cudaGetSymbolAddress((void**)&h0,   g_h0);
    cudaGetSymbolAddress((void**)&val,  g_val);
    cudaGetSymbolAddress((void**)&hup,  g_hup);
    cudaGetSymbolAddress((void**)&hA,   g_hA);
    cudaGetSymbolAddress((void**)&hB,   g_hB);
    cudaGetSymbolAddress((void**)&pa,   g_pa);
    cudaGetSymbolAddress((void**)&t1,   g_t1);
    cudaGetSymbolAddress((void**)&wdn,  g_wdn);
    cudaGetSymbolAddress((void**)&wup,  g_wup);
    cudaGetSymbolAddress((void**)&kidx, g_kidx);
    cudaGetSymbolAddress((void**)&kcnt, g_kcnt);
    cudaGetSymbolAddress((void**)&bwh,  g_bwh);
    cudaGetSymbolAddress((void**)&bwl,  g_bwl);

    cudaFuncSetAttribute(k_gemm<1,0,0,0>, cudaFuncAttributeMaxDynamicSharedMemorySize, GEMM_SMEM);
    cudaFuncSetAttribute(k_gemm<0,0,0,0>, cudaFuncAttributeMaxDynamicSharedMemorySize, GEMM_SMEM);
    cudaFuncSetAttribute(k_gemm<0,0,1,0>, cudaFuncAttributeMaxDynamicSharedMemorySize, GEMM_SMEM);
    cudaFuncSetAttribute(k_gemm<0,1,1,0>, cudaFuncAttributeMaxDynamicSharedMemorySize, GEMM_SMEM);
    cudaFuncSetAttribute(k_gemm<0,0,1,1>, cudaFuncAttributeMaxDynamicSharedMemorySize, GEMM_SMEM);
    cudaFuncSetAttribute(k_procatt, cudaFuncAttributeMaxDynamicSharedMemorySize, PROC_SMEM);

    const int M_IN  = BATCH * NIN;   // 65536
    const int M_LAT = BATCH * NLAT;  // 16384
    const size_t MS = (size_t)HID * HID;

    BWList L;
    L.w[0] = down_w;
    L.w[1] = pa_w;          L.w[2] = pa_w + 16384;  L.w[3] = pa_w + 32768;
    L.w[4] = up_w;
    L.w[5] = mlp1_w;        L.w[6] = mlp1_w + MS;   L.w[7] = mlp1_w + 2 * MS;
    L.w[8] = mlp2_w;        L.w[9] = mlp2_w + MS;   L.w[10] = mlp2_w + 2 * MS;
    L.w[11] = res_w;        L.w[12] = res_w + MS;   L.w[13] = res_w + 2 * MS;
    L.w[14] = de1_w;
    L.bre_mask = 0x1F;
    {
        dim3 g(64, NWMAT);
        k_prepB<<<g, 256>>>(L, bwh, bwl);
    }
    k_knn<<<NLAT, 256>>>(kidx, kcnt);
    k_factor<RLAT, RIN><<<NH, 256>>>(down_r, wdn);
    k_factor<RIN, RLAT><<<NH, 256>>>(up_r, wup);

#define BW(i) (bwh + (size_t)(i) * MS), (bwl + (size_t)(i) * MS)

    // ---- down: fused encoder + value GEMM, then separable attention ----
    k_gemm<1,0,0,0><<<M_IN / 128, 256, GEMM_SMEM>>>(
        nullptr, BW(0), nullptr, nullptr, nullptr,
        nullptr, nullptr, x, en_w, en_b, nullptr, nullptr, val);
    {
        dim3 g1(RIN / 8, BATCH, NH);
        k_sepY<RLAT, RIN><<<g1, 256>>>(val, wdn, h0);
        dim3 g2(RLAT, BATCH, NH);
        k_sepX<RLAT, RIN><<<g2, 256>>>(h0, wdn, hA);
    }

    // ---- processor blocks ----
    float* hin = hA;
    float* hout = hB;
    for (int i = 0; i < 3; i++) {
        k_gemm<0,0,0,0><<<M_LAT / 128, 256, GEMM_SMEM>>>(
            hin, BW(1 + i), nullptr, nullptr, nullptr,
            nullptr, nullptr, nullptr, nullptr, nullptr, nullptr, nullptr, val);
        {
            dim3 g(16, BATCH);
            k_procatt<<<g, 256, PROC_SMEM>>>(val, pa_r + i * NH, kidx, kcnt, pa);
        }
        k_gemm<0,0,1,0><<<M_LAT / 128, 256, GEMM_SMEM>>>(
            pa, BW(5 + i), nullptr, nullptr, nullptr,
            mlp1_b + i * HID, nullptr, nullptr, nullptr, nullptr, nullptr, nullptr, t1);
        k_gemm<0,1,1,0><<<M_LAT / 128, 256, GEMM_SMEM>>>(
            t1, BW(8 + i), hin, BW(11 + i),
            mlp2_b + i * HID, res_b + i * HID,
            nullptr, nullptr, nullptr, nullptr, nullptr, hout);
        float* tmp = hin; hin = hout; hout = tmp;
    }

    // ---- up: value GEMM + separable attention ----
    k_gemm<0,0,0,0><<<M_LAT / 128, 256, GEMM_SMEM>>>(
        hin, BW(4), nullptr, nullptr, nullptr,
        nullptr, nullptr, nullptr, nullptr, nullptr, nullptr, nullptr, val);
    {
        dim3 g1(RLAT / 8, BATCH, NH);
        k_sepY<RIN, RLAT><<<g1, 256>>>(val, wup, h0);
        dim3 g2(RIN, BATCH, NH);
        k_sepX<RIN, RLAT><<<g2, 256>>>(h0, wup, hup);
    }

    // ---- fused decoder ----
    k_gemm<0,0,1,1><<<M_IN / 128, 256, GEMM_SMEM>>>(
        hup, BW(14), nullptr, nullptr, nullptr,
        de1_b, nullptr, nullptr, nullptr, nullptr, de2_w, de2_b, out);
#undef BW
}